// round 2
// baseline (speedup 1.0000x reference)
#include <cuda_runtime.h>

// Problem constants
#define BB 64
#define NN 64
#define FA 75
#define FP 14
#define CC 128
#define NROWS_A (BB*NN)          // 4096 atom rows
#define ATOM_OUT (BB*NN*CC)      // 524288 floats (next_atom size)
#define LDB 132                  // padded row stride for 128-col smem buffers

// Scratch (device globals; no allocation allowed)
__device__ float g_U [NROWS_A*CC];
__device__ float g_V [NROWS_A*CC];
__device__ float g_a0[NROWS_A*CC];
__device__ float g_a1[NROWS_A*CC];

// ---------------------------------------------------------------------------
// Tiled GEMM core: M=64 rows (A in smem, row-major, stride lda),
// W is [K][128] in gmem (L2-resident), output accumulated into per-thread
// acc[4][8].  Thread map: tx = tid&15 -> cols tx*8..tx*8+7,
//                         ty = tid>>4 -> rows ty*4..ty*4+3.
// wtile: 32*128 floats of smem staging for W, double-buffered via registers.
// Ends with __syncthreads() so callers may immediately overwrite As.
// ---------------------------------------------------------------------------
__device__ __forceinline__ void load_chunk(const float* __restrict__ Wg, int K,
                                           int ch, float4 pre[4], int tid) {
#pragma unroll
    for (int j = 0; j < 4; ++j) {
        int idx4 = tid + j * 256;          // 0..1023
        int row  = idx4 >> 5;              // 0..31
        int col4 = idx4 & 31;              // 0..31 (float4 col)
        int gr   = ch * 32 + row;
        if (gr < K) pre[j] = *(const float4*)(Wg + gr * 128 + col4 * 4);
        else        pre[j] = make_float4(0.f, 0.f, 0.f, 0.f);
    }
}

__device__ __forceinline__ void store_chunk(float* wtile, const float4 pre[4],
                                            int tid) {
#pragma unroll
    for (int j = 0; j < 4; ++j) {
        int idx4 = tid + j * 256;
        *(float4*)(wtile + idx4 * 4) = pre[j];
    }
}

__device__ void gemm_acc(const float* __restrict__ As, int lda,
                         const float* __restrict__ Wg, int K,
                         float* wtile, float acc[4][8],
                         int tid, int tx, int ty) {
    float4 pre[4];
    int nch = (K + 31) >> 5;
    load_chunk(Wg, K, 0, pre, tid);
    for (int ch = 0; ch < nch; ++ch) {
        __syncthreads();                       // wtile free / As visible
        store_chunk(wtile, pre, tid);
        __syncthreads();
        if (ch + 1 < nch) load_chunk(Wg, K, ch + 1, pre, tid);
        int kc = K - ch * 32; if (kc > 32) kc = 32;
        const float* Ab = As + ch * 32;
        if (kc == 32) {
#pragma unroll 8
            for (int k = 0; k < 32; ++k) {
                float av[4];
#pragma unroll
                for (int m = 0; m < 4; ++m) av[m] = Ab[(ty * 4 + m) * lda + k];
                float4 q0 = *(const float4*)(wtile + k * 128 + tx * 8);
                float4 q1 = *(const float4*)(wtile + k * 128 + tx * 8 + 4);
                float bv[8] = {q0.x, q0.y, q0.z, q0.w, q1.x, q1.y, q1.z, q1.w};
#pragma unroll
                for (int m = 0; m < 4; ++m)
#pragma unroll
                    for (int n = 0; n < 8; ++n)
                        acc[m][n] = fmaf(av[m], bv[n], acc[m][n]);
            }
        } else {
            for (int k = 0; k < kc; ++k) {
                float av[4];
#pragma unroll
                for (int m = 0; m < 4; ++m) av[m] = Ab[(ty * 4 + m) * lda + k];
                float4 q0 = *(const float4*)(wtile + k * 128 + tx * 8);
                float4 q1 = *(const float4*)(wtile + k * 128 + tx * 8 + 4);
                float bv[8] = {q0.x, q0.y, q0.z, q0.w, q1.x, q1.y, q1.z, q1.w};
#pragma unroll
                for (int m = 0; m < 4; ++m)
#pragma unroll
                    for (int n = 0; n < 8; ++n)
                        acc[m][n] = fmaf(av[m], bv[n], acc[m][n]);
            }
        }
    }
    __syncthreads();   // safe for caller to overwrite As buffers
}

__device__ __forceinline__ void zero_acc(float acc[4][8]) {
#pragma unroll
    for (int m = 0; m < 4; ++m)
#pragma unroll
        for (int n = 0; n < 8; ++n) acc[m][n] = 0.f;
}

// relu(acc + bias) -> smem buffer (stride ldb)
__device__ __forceinline__ void epi_relu_smem(float* buf, int ldb,
                                              const float acc[4][8],
                                              const float* __restrict__ bias,
                                              int tx, int ty) {
    float bb[8];
#pragma unroll
    for (int n = 0; n < 8; ++n) bb[n] = bias[tx * 8 + n];
#pragma unroll
    for (int m = 0; m < 4; ++m) {
        int r = ty * 4 + m;
#pragma unroll
        for (int n = 0; n < 8; ++n) {
            float v = acc[m][n] + bb[n];
            buf[r * ldb + tx * 8 + n] = v > 0.f ? v : 0.f;
        }
    }
}

// relu(acc + bias) -> gmem rows [rowbase + r][128]
__device__ __forceinline__ void epi_relu_gmem(float* __restrict__ g, int rowbase,
                                              const float acc[4][8],
                                              const float* __restrict__ bias,
                                              int tx, int ty) {
    float bb[8];
#pragma unroll
    for (int n = 0; n < 8; ++n) bb[n] = bias[tx * 8 + n];
#pragma unroll
    for (int m = 0; m < 4; ++m) {
        int r = rowbase + ty * 4 + m;
#pragma unroll
        for (int n = 0; n < 8; ++n) {
            float v = acc[m][n] + bb[n];
            g[r * 128 + tx * 8 + n] = v > 0.f ? v : 0.f;
        }
    }
}

// raw acc -> gmem (no bias/relu), for U/V
__device__ __forceinline__ void epi_raw_gmem(float* __restrict__ g, int rowbase,
                                             const float acc[4][8],
                                             int tx, int ty) {
#pragma unroll
    for (int m = 0; m < 4; ++m) {
        int r = rowbase + ty * 4 + m;
#pragma unroll
        for (int n = 0; n < 8; ++n)
            g[r * 128 + tx * 8 + n] = acc[m][n];
    }
}

// ---------------------------------------------------------------------------
// Kernel A: per-b atom precompute.  a0 = MLP2(atom; a2a),  U = atom@a2pW0[:75],
// V = atom@a2pW0[75:].  Grid = 64 (one CTA per b), 256 threads.
// smem: atomS 64*80 | bufA 64*132 | wtile 32*128
// ---------------------------------------------------------------------------
extern "C" __global__ void __launch_bounds__(256)
kA(const float* __restrict__ atom_x,
   const float* __restrict__ a2a_W0, const float* __restrict__ a2a_b0,
   const float* __restrict__ a2a_W1, const float* __restrict__ a2a_b1,
   const float* __restrict__ a2p_W0) {
    extern __shared__ float sm[];
    float* atomS = sm;                    // 64*80
    float* bufA  = atomS + 64 * 80;       // 64*132
    float* wtile = bufA + 64 * LDB;       // 32*128
    int tid = threadIdx.x, tx = tid & 15, ty = tid >> 4;
    int b = blockIdx.x;

    for (int idx = tid; idx < 64 * FA; idx += 256) {
        int r = idx / FA, f = idx - r * FA;
        atomS[r * 80 + f] = atom_x[(b * 64 + r) * FA + f];
    }
    // first __syncthreads inside gemm_acc covers visibility of atomS

    float acc[4][8];
    // a0 = relu(relu(atom@W0+b0)@W1+b1)
    zero_acc(acc);
    gemm_acc(atomS, 80, a2a_W0, FA, wtile, acc, tid, tx, ty);
    epi_relu_smem(bufA, LDB, acc, a2a_b0, tx, ty);
    zero_acc(acc);
    gemm_acc(bufA, LDB, a2a_W1, CC, wtile, acc, tid, tx, ty);
    epi_relu_gmem(g_a0, b * 64, acc, a2a_b1, tx, ty);
    // U, V (raw, bias added later)
    zero_acc(acc);
    gemm_acc(atomS, 80, a2p_W0, FA, wtile, acc, tid, tx, ty);
    epi_raw_gmem(g_U, b * 64, acc, tx, ty);
    zero_acc(acc);
    gemm_acc(atomS, 80, a2p_W0 + FA * 128, FA, wtile, acc, tid, tx, ty);
    epi_raw_gmem(g_V, b * 64, acc, tx, ty);
}

// ---------------------------------------------------------------------------
// Kernel B: fused pair pipeline.  Grid = 4096 (one CTA per (b,i)), handles the
// 64 rows j=0..63.  Produces next_pair tile and a1[b,i] (p2a row-sum).
// smem: Ub 8192 | Vb 8192 | bufA 8448 | bufB 8448 | wtile 4096 | pxs 1024 | red 2112
// ---------------------------------------------------------------------------
extern "C" __global__ void __launch_bounds__(256)
kB(const float* __restrict__ pair_x,
   const float* __restrict__ p2a_W0, const float* __restrict__ p2a_b0,
   const float* __restrict__ p2a_W1, const float* __restrict__ p2a_b1,
   const float* __restrict__ a2p_b0, const float* __restrict__ a2p_W1,
   const float* __restrict__ a2p_b1,
   const float* __restrict__ p2p_W0, const float* __restrict__ p2p_b0,
   const float* __restrict__ p2p_W1, const float* __restrict__ p2p_b1,
   const float* __restrict__ pl_W0,  const float* __restrict__ pl_b0,
   const float* __restrict__ pl_W1,  const float* __restrict__ pl_b1,
   float* __restrict__ out_pair) {
    extern __shared__ float sm[];
    float* Ub    = sm;                    // 64*128
    float* Vb    = Ub + 8192;             // 64*128
    float* bufA  = Vb + 8192;             // 64*132
    float* bufB  = bufA + 64 * LDB;       // 64*132
    float* wtile = bufB + 64 * LDB;       // 32*128
    float* pxs   = wtile + 4096;          // 64*16
    float* red   = pxs + 1024;            // 16*132

    int tid = threadIdx.x, tx = tid & 15, ty = tid >> 4;
    int cta = blockIdx.x;
    int b = cta >> 6, i = cta & 63;

    {   // cooperative loads: U[b], V[b], pair_x rows (b,i,*)
        const float4* Ug = (const float4*)(g_U + b * 8192);
        const float4* Vg = (const float4*)(g_V + b * 8192);
        float4* Ub4 = (float4*)Ub;
        float4* Vb4 = (float4*)Vb;
        for (int idx = tid; idx < 2048; idx += 256) { Ub4[idx] = Ug[idx]; Vb4[idx] = Vg[idx]; }
        for (int idx = tid; idx < 64 * FP; idx += 256) {
            int j = idx / FP, f = idx - j * FP;
            pxs[j * 16 + f] = pair_x[((size_t)b * 4096 + i * 64 + j) * FP + f];
        }
    }

    float acc[4][8], acc2[4][8];

    // ---- p2a branch: y = relu(relu(px@W0+b0)@W1+b1); a1[b,i] = sum_j y[j] ----
    zero_acc(acc);
    gemm_acc(pxs, 16, p2a_W0, FP, wtile, acc, tid, tx, ty);
    epi_relu_smem(bufA, LDB, acc, p2a_b0, tx, ty);
    zero_acc(acc);
    gemm_acc(bufA, LDB, p2a_W1, CC, wtile, acc, tid, tx, ty);
    {
        float bb[8], part[8];
#pragma unroll
        for (int n = 0; n < 8; ++n) { bb[n] = p2a_b1[tx * 8 + n]; part[n] = 0.f; }
#pragma unroll
        for (int m = 0; m < 4; ++m)
#pragma unroll
            for (int n = 0; n < 8; ++n) {
                float v = acc[m][n] + bb[n];
                part[n] += (v > 0.f ? v : 0.f);
            }
#pragma unroll
        for (int n = 0; n < 8; ++n) red[ty * LDB + tx * 8 + n] = part[n];
        __syncthreads();
        if (tid < 128) {
            float s = 0.f;
#pragma unroll
            for (int t = 0; t < 16; ++t) s += red[t * LDB + tid];
            g_a1[(b * 64 + i) * 128 + tid] = s;
        }
    }

    // ---- p2p branch: p1 -> bufB ----
    zero_acc(acc);
    gemm_acc(pxs, 16, p2p_W0, FP, wtile, acc, tid, tx, ty);
    epi_relu_smem(bufA, LDB, acc, p2p_b0, tx, ty);
    zero_acc(acc);
    gemm_acc(bufA, LDB, p2p_W1, CC, wtile, acc, tid, tx, ty);
    epi_relu_smem(bufB, LDB, acc, p2p_b1, tx, ty);   // bufB = p1

    // ---- a2p branch (factorized first layer) ----
    // h0[j] = relu(U[i] + V[j] + b0a)
    for (int idx = tid; idx < 8192; idx += 256) {
        int j = idx >> 7, c = idx & 127;
        float v = Ub[i * 128 + c] + Vb[j * 128 + c] + a2p_b0[c];
        bufA[j * LDB + c] = v > 0.f ? v : 0.f;
    }
    zero_acc(acc);
    gemm_acc(bufA, LDB, a2p_W1, CC, wtile, acc, tid, tx, ty);
    // h1[j] = relu(U[j] + V[i] + b0a)   (gemm_acc's trailing sync makes this safe)
    for (int idx = tid; idx < 8192; idx += 256) {
        int j = idx >> 7, c = idx & 127;
        float v = Ub[j * 128 + c] + Vb[i * 128 + c] + a2p_b0[c];
        bufA[j * LDB + c] = v > 0.f ? v : 0.f;
    }
    zero_acc(acc2);
    gemm_acc(bufA, LDB, a2p_W1, CC, wtile, acc2, tid, tx, ty);
    {   // p0 = relu(y0+b1a) + relu(y1+b1a) -> bufA
        float bb[8];
#pragma unroll
        for (int n = 0; n < 8; ++n) bb[n] = a2p_b1[tx * 8 + n];
#pragma unroll
        for (int m = 0; m < 4; ++m) {
            int r = ty * 4 + m;
#pragma unroll
            for (int n = 0; n < 8; ++n) {
                float v1 = acc[m][n] + bb[n];  v1 = v1 > 0.f ? v1 : 0.f;
                float v2 = acc2[m][n] + bb[n]; v2 = v2 > 0.f ? v2 : 0.f;
                bufA[r * LDB + tx * 8 + n] = v1 + v2;
            }
        }
    }

    // ---- pair layer: h = relu(p0@Wl0[:128] + p1@Wl0[128:] + b0l) ----
    zero_acc(acc);
    gemm_acc(bufA, LDB, pl_W0, CC, wtile, acc, tid, tx, ty);
    gemm_acc(bufB, LDB, pl_W0 + 128 * 128, CC, wtile, acc, tid, tx, ty);
    epi_relu_smem(bufA, LDB, acc, pl_b0, tx, ty);
    // out = relu(h@Wl1 + b1l)  (relu∘relu == relu)
    zero_acc(acc);
    gemm_acc(bufA, LDB, pl_W1, CC, wtile, acc, tid, tx, ty);
    {
        float bb[8];
#pragma unroll
        for (int n = 0; n < 8; ++n) bb[n] = pl_b1[tx * 8 + n];
        size_t rowbase = (size_t)b * 4096 + i * 64;
#pragma unroll
        for (int m = 0; m < 4; ++m) {
            size_t r = rowbase + ty * 4 + m;
#pragma unroll
            for (int n = 0; n < 8; ++n) {
                float v = acc[m][n] + bb[n];
                out_pair[r * 128 + tx * 8 + n] = v > 0.f ? v : 0.f;
            }
        }
    }
}

// ---------------------------------------------------------------------------
// Kernel C: atom finalize.  next_atom = relu(MLP2(concat(a0,a1); al)).
// Grid = 64 (one CTA per b).
// smem: in0 8192 | in1 8192 | bufA 8448 | wtile 4096
// ---------------------------------------------------------------------------
extern "C" __global__ void __launch_bounds__(256)
kC(const float* __restrict__ al_W0, const float* __restrict__ al_b0,
   const float* __restrict__ al_W1, const float* __restrict__ al_b1,
   float* __restrict__ out_atom) {
    extern __shared__ float sm[];
    float* in0   = sm;                    // 64*128
    float* in1   = in0 + 8192;            // 64*128
    float* bufA  = in1 + 8192;            // 64*132
    float* wtile = bufA + 64 * LDB;       // 32*128
    int tid = threadIdx.x, tx = tid & 15, ty = tid >> 4;
    int b = blockIdx.x;

    {
        const float4* g0 = (const float4*)(g_a0 + b * 8192);
        const float4* g1 = (const float4*)(g_a1 + b * 8192);
        float4* s0 = (float4*)in0;
        float4* s1 = (float4*)in1;
        for (int idx = tid; idx < 2048; idx += 256) { s0[idx] = g0[idx]; s1[idx] = g1[idx]; }
    }

    float acc[4][8];
    zero_acc(acc);
    gemm_acc(in0, 128, al_W0, CC, wtile, acc, tid, tx, ty);
    gemm_acc(in1, 128, al_W0 + 128 * 128, CC, wtile, acc, tid, tx, ty);
    epi_relu_smem(bufA, LDB, acc, al_b0, tx, ty);
    zero_acc(acc);
    gemm_acc(bufA, LDB, al_W1, CC, wtile, acc, tid, tx, ty);
    epi_relu_gmem(out_atom, b * 64, acc, al_b1, tx, ty);
}

// ---------------------------------------------------------------------------
extern "C" void kernel_launch(void* const* d_in, const int* in_sizes, int n_in,
                              void* d_out, int out_size) {
    const float* atom_x = (const float*)d_in[0];
    const float* pair_x = (const float*)d_in[1];
    const float* a2a_W0 = (const float*)d_in[2];
    const float* a2a_b0 = (const float*)d_in[3];
    const float* a2a_W1 = (const float*)d_in[4];
    const float* a2a_b1 = (const float*)d_in[5];
    const float* p2a_W0 = (const float*)d_in[6];
    const float* p2a_b0 = (const float*)d_in[7];
    const float* p2a_W1 = (const float*)d_in[8];
    const float* p2a_b1 = (const float*)d_in[9];
    const float* al_W0  = (const float*)d_in[10];
    const float* al_b0  = (const float*)d_in[11];
    const float* al_W1  = (const float*)d_in[12];
    const float* al_b1  = (const float*)d_in[13];
    const float* a2p_W0 = (const float*)d_in[14];
    const float* a2p_b0 = (const float*)d_in[15];
    const float* a2p_W1 = (const float*)d_in[16];
    const float* a2p_b1 = (const float*)d_in[17];
    const float* p2p_W0 = (const float*)d_in[18];
    const float* p2p_b0 = (const float*)d_in[19];
    const float* p2p_W1 = (const float*)d_in[20];
    const float* p2p_b1 = (const float*)d_in[21];
    const float* pl_W0  = (const float*)d_in[22];
    const float* pl_b0  = (const float*)d_in[23];
    const float* pl_W1  = (const float*)d_in[24];
    const float* pl_b1  = (const float*)d_in[25];
    float* out = (float*)d_out;

    const int SMEM_A = (64 * 80 + 64 * LDB + 32 * 128) * 4;                       // ~70.6 KB
    const int SMEM_B = (8192 + 8192 + 64 * LDB + 64 * LDB + 4096 + 1024 + 16 * LDB) * 4; // ~162 KB
    const int SMEM_C = (8192 + 8192 + 64 * LDB + 32 * 128) * 4;                   // ~115.7 KB

    cudaFuncSetAttribute(kA, cudaFuncAttributeMaxDynamicSharedMemorySize, SMEM_A);
    cudaFuncSetAttribute(kB, cudaFuncAttributeMaxDynamicSharedMemorySize, SMEM_B);
    cudaFuncSetAttribute(kC, cudaFuncAttributeMaxDynamicSharedMemorySize, SMEM_C);

    kA<<<64, 256, SMEM_A>>>(atom_x, a2a_W0, a2a_b0, a2a_W1, a2a_b1, a2p_W0);
    kB<<<4096, 256, SMEM_B>>>(pair_x,
                              p2a_W0, p2a_b0, p2a_W1, p2a_b1,
                              a2p_b0, a2p_W1, a2p_b1,
                              p2p_W0, p2p_b0, p2p_W1, p2p_b1,
                              pl_W0, pl_b0, pl_W1, pl_b1,
                              out + ATOM_OUT);
    kC<<<64, 256, SMEM_C>>>(al_W0, al_b0, al_W1, al_b1, out);
}

// round 5
// speedup vs baseline: 3.7380x; 3.7380x over previous
#include <cuda_runtime.h>
#include <cstdint>

#define BB 64
#define NN 64
#define FA 75
#define FP 14
#define CC 128
#define NROWS_A (BB*NN)
#define ATOM_OUT (BB*NN*CC)

// ---------------- global scratch ----------------
__device__ float g_U [NROWS_A*CC];
__device__ float g_V [NROWS_A*CC];
__device__ float g_a0[NROWS_A*CC];
__device__ float g_a1[NROWS_A*CC];

// transposed ([N=128][K]) tf32-rounded, zero-padded weights
__device__ float g_Wp2a0[128*16];
__device__ float g_Wp2a1[128*128];
__device__ float g_Wp2p0[128*16];
__device__ float g_Wp2p1[128*128];
__device__ float g_Wa2p1[128*128];
__device__ float g_Wpl0a[128*128];
__device__ float g_Wpl0b[128*128];
__device__ float g_Wpl1 [128*128];
__device__ float g_Wal0a[128*128];
__device__ float g_Wal0b[128*128];
__device__ float g_Wal1 [128*128];
__device__ float g_Wa2a0 [128*80];
__device__ float g_Wa2a1 [128*128];
__device__ float g_Wa2p0a[128*80];
__device__ float g_Wa2p0b[128*80];

// ---------------- helpers ----------------
__device__ __forceinline__ uint32_t smem_u32(const void* p){
    uint32_t a;
    asm("{ .reg .u64 t; cvta.to.shared.u64 t, %1; cvt.u32.u64 %0, t; }" : "=r"(a) : "l"(p));
    return a;
}
__device__ __forceinline__ float to_tf32(float x){
    float r; asm("cvt.rna.tf32.f32 %0, %1;" : "=f"(r) : "f"(x)); return r;
}
__device__ __forceinline__ void mma_tf32(float c[4], const uint32_t a[4], const uint32_t b[2]){
    asm volatile("mma.sync.aligned.m16n8k8.row.col.f32.tf32.tf32.f32 "
        "{%0,%1,%2,%3}, {%4,%5,%6,%7}, {%8,%9}, {%0,%1,%2,%3};"
        : "+f"(c[0]), "+f"(c[1]), "+f"(c[2]), "+f"(c[3])
        : "r"(a[0]), "r"(a[1]), "r"(a[2]), "r"(a[3]), "r"(b[0]), "r"(b[1]));
}
__device__ __forceinline__ void zacc(float (&a)[4][4][4]){
#pragma unroll
    for (int m = 0; m < 4; ++m)
#pragma unroll
        for (int n = 0; n < 4; ++n)
#pragma unroll
            for (int q = 0; q < 4; ++q) a[m][n][q] = 0.f;
}

// Warp-group GEMM: 8 warps compute 128x128 += A(128xK) @ B(128xK)^T
// warp (wm = w&1, wn = w>>1) -> rows wm*64..+63, cols wn*32..+31
// lda/ldb strides (floats) must satisfy stride%32 in {4,20} for conflict-free LDS.
template<int KSTEPS>
__device__ __forceinline__ void wg_mma(float (&acc)[4][4][4],
        const uint32_t* __restrict__ As, int lda,
        const uint32_t* __restrict__ Bs, int ldb,
        int wm, int wn, int lane){
    const uint32_t* Ap = As + (wm * 64 + (lane >> 2)) * lda + (lane & 3);
    const uint32_t* Bp = Bs + (wn * 32 + (lane >> 2)) * ldb + (lane & 3);
#pragma unroll
    for (int ks = 0; ks < KSTEPS; ++ks){
        int k0 = ks * 8;
        uint32_t a[4][4], bf[4][2];
#pragma unroll
        for (int mf = 0; mf < 4; ++mf){
            const uint32_t* p = Ap + mf * 16 * lda + k0;
            a[mf][0] = p[0]; a[mf][1] = p[8 * lda]; a[mf][2] = p[4]; a[mf][3] = p[8 * lda + 4];
        }
#pragma unroll
        for (int nf = 0; nf < 4; ++nf){
            const uint32_t* p = Bp + nf * 8 * ldb + k0;
            bf[nf][0] = p[0]; bf[nf][1] = p[4];
        }
#pragma unroll
        for (int mf = 0; mf < 4; ++mf)
#pragma unroll
            for (int nf = 0; nf < 4; ++nf)
                mma_tf32(acc[mf][nf], a[mf], bf[nf]);
    }
}

// relu(acc + bias) -> smem (stride ldd), optional tf32 rounding
__device__ __forceinline__ void epi_smem(const float (&acc)[4][4][4], float* dst, int ldd,
        const float* __restrict__ bias, int wm, int wn, int lane, bool rnd){
    int r0 = wm * 64 + (lane >> 2);
    int c0 = wn * 32 + 2 * (lane & 3);
#pragma unroll
    for (int mf = 0; mf < 4; ++mf)
#pragma unroll
        for (int nf = 0; nf < 4; ++nf){
            int c = c0 + nf * 8;
            float bx = bias[c], by = bias[c + 1];
            int ra = r0 + mf * 16, rb = ra + 8;
            float v0 = fmaxf(acc[mf][nf][0] + bx, 0.f);
            float v1 = fmaxf(acc[mf][nf][1] + by, 0.f);
            float v2 = fmaxf(acc[mf][nf][2] + bx, 0.f);
            float v3 = fmaxf(acc[mf][nf][3] + by, 0.f);
            if (rnd){ v0 = to_tf32(v0); v1 = to_tf32(v1); v2 = to_tf32(v2); v3 = to_tf32(v3); }
            *(float2*)(dst + ra * ldd + c) = make_float2(v0, v1);
            *(float2*)(dst + rb * ldd + c) = make_float2(v2, v3);
        }
}

// relu(acc + bias) -> gmem 128x128 contiguous tile
__device__ __forceinline__ void epi_gmem_relu(const float (&acc)[4][4][4], float* __restrict__ dst,
        const float* __restrict__ bias, int wm, int wn, int lane){
    int r0 = wm * 64 + (lane >> 2);
    int c0 = wn * 32 + 2 * (lane & 3);
#pragma unroll
    for (int mf = 0; mf < 4; ++mf)
#pragma unroll
        for (int nf = 0; nf < 4; ++nf){
            int c = c0 + nf * 8;
            float bx = bias[c], by = bias[c + 1];
            int ra = r0 + mf * 16, rb = ra + 8;
            *(float2*)(dst + ra * 128 + c) = make_float2(fmaxf(acc[mf][nf][0] + bx, 0.f),
                                                         fmaxf(acc[mf][nf][1] + by, 0.f));
            *(float2*)(dst + rb * 128 + c) = make_float2(fmaxf(acc[mf][nf][2] + bx, 0.f),
                                                         fmaxf(acc[mf][nf][3] + by, 0.f));
        }
}

// raw acc -> gmem 128x128 contiguous tile
__device__ __forceinline__ void epi_gmem_raw(const float (&acc)[4][4][4], float* __restrict__ dst,
        int wm, int wn, int lane){
    int r0 = wm * 64 + (lane >> 2);
    int c0 = wn * 32 + 2 * (lane & 3);
#pragma unroll
    for (int mf = 0; mf < 4; ++mf)
#pragma unroll
        for (int nf = 0; nf < 4; ++nf){
            int c = c0 + nf * 8;
            int ra = r0 + mf * 16, rb = ra + 8;
            *(float2*)(dst + ra * 128 + c) = make_float2(acc[mf][nf][0], acc[mf][nf][1]);
            *(float2*)(dst + rb * 128 + c) = make_float2(acc[mf][nf][2], acc[mf][nf][3]);
        }
}

// async copy dense [128][K] gmem -> smem stride 132
__device__ __forceinline__ void cpa132(float* dstS, const float* src, int K, int tid){
    size_t gp = __cvta_generic_to_global(src);
    uint32_t base = smem_u32(dstS);
    int kf4 = K >> 2;
    int nf4 = 128 * kf4;
    for (int i = tid; i < nf4; i += 256){
        int n = i / kf4, k4 = i - n * kf4;
        uint32_t d = base + (uint32_t)(n * 132 + k4 * 4) * 4u;
        asm volatile("cp.async.ca.shared.global [%0], [%1], 16;" :: "r"(d), "l"(gp + (size_t)i * 16) : "memory");
    }
    asm volatile("cp.async.commit_group;" ::: "memory");
}
__device__ __forceinline__ void cpa_wait(){
    asm volatile("cp.async.wait_group 0;" ::: "memory");
}

// ---------------- weight prep ----------------
__device__ __forceinline__ void wprep(float* dst, const float* src, int Kpad, int Ksrc, int tid){
    for (int i = tid; i < 128 * Kpad; i += 256){
        int n = i / Kpad, k = i - n * Kpad;
        dst[i] = to_tf32(k < Ksrc ? src[k * 128 + n] : 0.f);
    }
}
extern "C" __global__ void kW(const float* __restrict__ p2aW0, const float* __restrict__ p2aW1,
                              const float* __restrict__ p2pW0, const float* __restrict__ p2pW1,
                              const float* __restrict__ a2pW1, const float* __restrict__ plW0,
                              const float* __restrict__ plW1,  const float* __restrict__ alW0,
                              const float* __restrict__ alW1,  const float* __restrict__ a2aW0,
                              const float* __restrict__ a2aW1, const float* __restrict__ a2pW0){
    int t = blockIdx.x, tid = threadIdx.x;
    switch (t){
        case 0:  wprep(g_Wp2a0,  p2aW0,            16, FP,  tid); break;
        case 1:  wprep(g_Wp2a1,  p2aW1,           128, 128, tid); break;
        case 2:  wprep(g_Wp2p0,  p2pW0,            16, FP,  tid); break;
        case 3:  wprep(g_Wp2p1,  p2pW1,           128, 128, tid); break;
        case 4:  wprep(g_Wa2p1,  a2pW1,           128, 128, tid); break;
        case 5:  wprep(g_Wpl0a,  plW0,            128, 128, tid); break;
        case 6:  wprep(g_Wpl0b,  plW0 + 128*128,  128, 128, tid); break;
        case 7:  wprep(g_Wpl1,   plW1,            128, 128, tid); break;
        case 8:  wprep(g_Wal0a,  alW0,            128, 128, tid); break;
        case 9:  wprep(g_Wal0b,  alW0 + 128*128,  128, 128, tid); break;
        case 10: wprep(g_Wal1,   alW1,            128, 128, tid); break;
        case 11: wprep(g_Wa2a0,  a2aW0,            80, FA,  tid); break;
        case 12: wprep(g_Wa2a1,  a2aW1,           128, 128, tid); break;
        case 13: wprep(g_Wa2p0a, a2pW0,            80, FA,  tid); break;
        default: wprep(g_Wa2p0b, a2pW0 + FA*128,   80, FA,  tid); break;
    }
}

// ---------------- kernel A: atom precompute (mma) ----------------
// grid (32, 3): blk covers batches 2*blk, 2*blk+1 (128 rows). task y:
//   0: a0 = MLP2(atom; a2a) -> g_a0 ; 1: U = atom@a2pW0[:75] ; 2: V = atom@a2pW0[75:]
// smem: As 128*84 | act 128*132 | Bw 128*132
extern "C" __global__ void __launch_bounds__(256, 1)
kA(const float* __restrict__ atom_x,
   const float* __restrict__ a2a_b0, const float* __restrict__ a2a_b1){
    extern __shared__ float sm[];
    float* As  = sm;                 // 128*84
    float* act = As + 128 * 84;      // 128*132
    float* Bw  = act + 128 * 132;    // 128*132
    int tid = threadIdx.x, lane = tid & 31, w = tid >> 5;
    int wm = w & 1, wn = w >> 1;
    int blk = blockIdx.x, task = blockIdx.y;

    for (int i = tid; i < 128 * 80; i += 256){
        int r = i / 80, k = i - r * 80;
        float v = (k < FA) ? atom_x[(blk * 128 + r) * FA + k] : 0.f;
        As[r * 84 + k] = to_tf32(v);
    }
    const float* w0 = (task == 0) ? g_Wa2a0 : (task == 1 ? g_Wa2p0a : g_Wa2p0b);
    cpa132(Bw, w0, 80, tid);
    cpa_wait();
    __syncthreads();

    float acc[4][4][4];
    zacc(acc);
    wg_mma<10>(acc, (const uint32_t*)As, 84, (const uint32_t*)Bw, 132, wm, wn, lane);
    if (task == 0){
        __syncthreads();
        cpa132(Bw, g_Wa2a1, 128, tid);
        epi_smem(acc, act, 132, a2a_b0, wm, wn, lane, true);
        cpa_wait();
        __syncthreads();
        zacc(acc);
        wg_mma<16>(acc, (const uint32_t*)act, 132, (const uint32_t*)Bw, 132, wm, wn, lane);
        epi_gmem_relu(acc, g_a0 + blk * 16384, a2a_b1, wm, wn, lane);
    } else {
        float* dst = (task == 1 ? g_U : g_V) + blk * 16384;
        epi_gmem_raw(acc, dst, wm, wn, lane);
    }
}

// ---------------- kernel B: fused pair pipeline (mma) ----------------
// grid 2048: CTA per (b, i2); rows r in [0,128): ih = 2*i2 + (r>>6), j = r&63.
// smem: act 128*132 | Bw 128*132 | pxs 128*20   (~142 KB)
extern "C" __global__ void __launch_bounds__(256, 1)
kB(const float* __restrict__ pair_x,
   const float* __restrict__ p2a_b0, const float* __restrict__ p2a_b1,
   const float* __restrict__ p2p_b0, const float* __restrict__ p2p_b1,
   const float* __restrict__ a2p_b0, const float* __restrict__ a2p_b1,
   const float* __restrict__ pl_b0,  const float* __restrict__ pl_b1,
   float* __restrict__ out_pair){
    extern __shared__ float sm[];
    float* act = sm;                 // 128*132
    float* Bw  = act + 128 * 132;    // 128*132
    float* pxs = Bw + 128 * 132;     // 128*20
    int tid = threadIdx.x, lane = tid & 31, w = tid >> 5;
    int wm = w & 1, wn = w >> 1;
    int cta = blockIdx.x;
    int b = cta >> 5, i2 = cta & 31;
    size_t tilebase = (size_t)b * 4096 + (size_t)i2 * 128;     // global pair-row base
    const float* gU = g_U + b * 8192;
    const float* gV = g_V + b * 8192;

    float accT[4][4][4], accC[4][4][4];

    // ---- build pxs + first weights ----
    cpa132(Bw, g_Wp2a0, 16, tid);
    for (int i = tid; i < 128 * 16; i += 256){
        int r = i >> 4, k = i & 15;
        float v = (k < FP) ? pair_x[(tilebase + r) * FP + k] : 0.f;
        pxs[r * 20 + k] = to_tf32(v);
    }
    cpa_wait();
    __syncthreads();

    // ---- G1: px @ p2aW0 ----
    zacc(accT);
    wg_mma<2>(accT, (const uint32_t*)pxs, 20, (const uint32_t*)Bw, 132, wm, wn, lane);
    __syncthreads();
    cpa132(Bw, g_Wp2a1, 128, tid);
    epi_smem(accT, act, 132, p2a_b0, wm, wn, lane, true);
    cpa_wait();
    __syncthreads();

    // ---- G2: act @ p2aW1 ; epilogue = relu + column sum -> g_a1 ----
    zacc(accT);
    wg_mma<16>(accT, (const uint32_t*)act, 132, (const uint32_t*)Bw, 132, wm, wn, lane);
    __syncthreads();
    cpa132(Bw, g_Wp2p0, 16, tid);
    {
        int c0 = wn * 32 + 2 * (lane & 3);
#pragma unroll
        for (int nf = 0; nf < 4; ++nf){
            int c = c0 + nf * 8;
            float bx = p2a_b1[c], by = p2a_b1[c + 1];
            float s0 = 0.f, s1 = 0.f;
#pragma unroll
            for (int mf = 0; mf < 4; ++mf){
                s0 += fmaxf(accT[mf][nf][0] + bx, 0.f) + fmaxf(accT[mf][nf][2] + bx, 0.f);
                s1 += fmaxf(accT[mf][nf][1] + by, 0.f) + fmaxf(accT[mf][nf][3] + by, 0.f);
            }
#pragma unroll
            for (int off = 4; off < 32; off <<= 1){
                s0 += __shfl_xor_sync(0xFFFFFFFFu, s0, off);
                s1 += __shfl_xor_sync(0xFFFFFFFFu, s1, off);
            }
            if (lane < 4){
                float* gr = g_a1 + ((size_t)b * 64 + i2 * 2 + wm) * 128 + c;
                gr[0] = s0; gr[1] = s1;
            }
        }
    }
    cpa_wait();
    __syncthreads();

    // ---- G3: px @ p2pW0 ----
    zacc(accT);
    wg_mma<2>(accT, (const uint32_t*)pxs, 20, (const uint32_t*)Bw, 132, wm, wn, lane);
    __syncthreads();
    cpa132(Bw, g_Wp2p1, 128, tid);
    epi_smem(accT, act, 132, p2p_b0, wm, wn, lane, true);
    cpa_wait();
    __syncthreads();

    // ---- G4: act @ p2pW1 -> act = p1 ----
    zacc(accT);
    wg_mma<16>(accT, (const uint32_t*)act, 132, (const uint32_t*)Bw, 132, wm, wn, lane);
    __syncthreads();
    cpa132(Bw, g_Wpl0b, 128, tid);
    epi_smem(accT, act, 132, p2p_b1, wm, wn, lane, true);
    cpa_wait();
    __syncthreads();

    // ---- G5: p1 @ plW0b -> accC (persistent) ----
    zacc(accC);
    wg_mma<16>(accC, (const uint32_t*)act, 132, (const uint32_t*)Bw, 132, wm, wn, lane);
    __syncthreads();
    cpa132(Bw, g_Wa2p1, 128, tid);
    // build h0 = relu(U[ih] + V[j] + b0a)
    for (int i = tid; i < 128 * 32; i += 256){
        int r = i >> 5, c4 = (i & 31) << 2;
        int ih = i2 * 2 + (r >> 6), j = r & 63;
        float4 uu = *(const float4*)(gU + ih * 128 + c4);
        float4 vv = *(const float4*)(gV + j  * 128 + c4);
        float4 bb = *(const float4*)(a2p_b0 + c4);
        float4 o;
        o.x = to_tf32(fmaxf(uu.x + vv.x + bb.x, 0.f));
        o.y = to_tf32(fmaxf(uu.y + vv.y + bb.y, 0.f));
        o.z = to_tf32(fmaxf(uu.z + vv.z + bb.z, 0.f));
        o.w = to_tf32(fmaxf(uu.w + vv.w + bb.w, 0.f));
        *(float4*)(act + r * 132 + c4) = o;
    }
    cpa_wait();
    __syncthreads();

    // ---- G6: h0 @ a2pW1 -> accT ; epi relu -> act ----
    zacc(accT);
    wg_mma<16>(accT, (const uint32_t*)act, 132, (const uint32_t*)Bw, 132, wm, wn, lane);
    __syncthreads();
    cpa132(Bw, g_Wpl0a, 128, tid);
    epi_smem(accT, act, 132, a2p_b1, wm, wn, lane, true);
    cpa_wait();
    __syncthreads();

    // ---- G7a: relu(y0) @ plW0a -> accC += ----
    wg_mma<16>(accC, (const uint32_t*)act, 132, (const uint32_t*)Bw, 132, wm, wn, lane);
    __syncthreads();
    cpa132(Bw, g_Wa2p1, 128, tid);
    // build h1 = relu(U[j] + V[ih] + b0a)
    for (int i = tid; i < 128 * 32; i += 256){
        int r = i >> 5, c4 = (i & 31) << 2;
        int ih = i2 * 2 + (r >> 6), j = r & 63;
        float4 uu = *(const float4*)(gU + j  * 128 + c4);
        float4 vv = *(const float4*)(gV + ih * 128 + c4);
        float4 bb = *(const float4*)(a2p_b0 + c4);
        float4 o;
        o.x = to_tf32(fmaxf(uu.x + vv.x + bb.x, 0.f));
        o.y = to_tf32(fmaxf(uu.y + vv.y + bb.y, 0.f));
        o.z = to_tf32(fmaxf(uu.z + vv.z + bb.z, 0.f));
        o.w = to_tf32(fmaxf(uu.w + vv.w + bb.w, 0.f));
        *(float4*)(act + r * 132 + c4) = o;
    }
    cpa_wait();
    __syncthreads();

    // ---- G8: h1 @ a2pW1 -> accT ; epi relu -> act ----
    zacc(accT);
    wg_mma<16>(accT, (const uint32_t*)act, 132, (const uint32_t*)Bw, 132, wm, wn, lane);
    __syncthreads();
    cpa132(Bw, g_Wpl0a, 128, tid);
    epi_smem(accT, act, 132, a2p_b1, wm, wn, lane, true);
    cpa_wait();
    __syncthreads();

    // ---- G7b: relu(y1) @ plW0a -> accC += ; epi accC relu -> act ----
    wg_mma<16>(accC, (const uint32_t*)act, 132, (const uint32_t*)Bw, 132, wm, wn, lane);
    __syncthreads();
    cpa132(Bw, g_Wpl1, 128, tid);
    epi_smem(accC, act, 132, pl_b0, wm, wn, lane, true);
    cpa_wait();
    __syncthreads();

    // ---- G9: act @ plW1 -> out ----
    zacc(accT);
    wg_mma<16>(accT, (const uint32_t*)act, 132, (const uint32_t*)Bw, 132, wm, wn, lane);
    epi_gmem_relu(accT, out_pair + tilebase * 128, pl_b1, wm, wn, lane);
}

// ---------------- kernel C: atom finalize (mma) ----------------
// grid 32: blk covers batches 2*blk, 2*blk+1 (128 rows).
// smem: As 128*132 | Bw 128*132
extern "C" __global__ void __launch_bounds__(256, 1)
kC(const float* __restrict__ al_b0, const float* __restrict__ al_b1,
   float* __restrict__ out_atom){
    extern __shared__ float sm[];
    float* As = sm;                  // 128*132
    float* Bw = As + 128 * 132;      // 128*132
    int tid = threadIdx.x, lane = tid & 31, w = tid >> 5;
    int wm = w & 1, wn = w >> 1;
    int blk = blockIdx.x;

    float acc[4][4][4];

    cpa132(Bw, g_Wal0a, 128, tid);
    for (int i = tid; i < 128 * 32; i += 256){
        int r = i >> 5, c4 = (i & 31) << 2;
        float4 v = *(const float4*)(g_a0 + blk * 16384 + r * 128 + c4);
        v.x = to_tf32(v.x); v.y = to_tf32(v.y); v.z = to_tf32(v.z); v.w = to_tf32(v.w);
        *(float4*)(As + r * 132 + c4) = v;
    }
    cpa_wait();
    __syncthreads();

    zacc(acc);
    wg_mma<16>(acc, (const uint32_t*)As, 132, (const uint32_t*)Bw, 132, wm, wn, lane);
    __syncthreads();
    cpa132(Bw, g_Wal0b, 128, tid);
    for (int i = tid; i < 128 * 32; i += 256){
        int r = i >> 5, c4 = (i & 31) << 2;
        float4 v = *(const float4*)(g_a1 + blk * 16384 + r * 128 + c4);
        v.x = to_tf32(v.x); v.y = to_tf32(v.y); v.z = to_tf32(v.z); v.w = to_tf32(v.w);
        *(float4*)(As + r * 132 + c4) = v;
    }
    cpa_wait();
    __syncthreads();

    wg_mma<16>(acc, (const uint32_t*)As, 132, (const uint32_t*)Bw, 132, wm, wn, lane);
    __syncthreads();
    cpa132(Bw, g_Wal1, 128, tid);
    epi_smem(acc, As, 132, al_b0, wm, wn, lane, true);
    cpa_wait();
    __syncthreads();

    zacc(acc);
    wg_mma<16>(acc, (const uint32_t*)As, 132, (const uint32_t*)Bw, 132, wm, wn, lane);
    epi_gmem_relu(acc, out_atom + blk * 16384, al_b1, wm, wn, lane);
}

// ---------------------------------------------------------------------------
extern "C" void kernel_launch(void* const* d_in, const int* in_sizes, int n_in,
                              void* d_out, int out_size) {
    const float* atom_x = (const float*)d_in[0];
    const float* pair_x = (const float*)d_in[1];
    const float* a2a_W0 = (const float*)d_in[2];
    const float* a2a_b0 = (const float*)d_in[3];
    const float* a2a_W1 = (const float*)d_in[4];
    const float* a2a_b1 = (const float*)d_in[5];
    const float* p2a_W0 = (const float*)d_in[6];
    const float* p2a_b0 = (const float*)d_in[7];
    const float* p2a_W1 = (const float*)d_in[8];
    const float* p2a_b1 = (const float*)d_in[9];
    const float* al_W0  = (const float*)d_in[10];
    const float* al_b0  = (const float*)d_in[11];
    const float* al_W1  = (const float*)d_in[12];
    const float* al_b1  = (const float*)d_in[13];
    const float* a2p_W0 = (const float*)d_in[14];
    const float* a2p_b0 = (const float*)d_in[15];
    const float* a2p_W1 = (const float*)d_in[16];
    const float* a2p_b1 = (const float*)d_in[17];
    const float* p2p_W0 = (const float*)d_in[18];
    const float* p2p_b0 = (const float*)d_in[19];
    const float* p2p_W1 = (const float*)d_in[20];
    const float* p2p_b1 = (const float*)d_in[21];
    const float* pl_W0  = (const float*)d_in[22];
    const float* pl_b0  = (const float*)d_in[23];
    const float* pl_W1  = (const float*)d_in[24];
    const float* pl_b1  = (const float*)d_in[25];
    float* out = (float*)d_out;

    const int SMEM_A = (128 * 84 + 128 * 132 + 128 * 132) * 4;   // ~178 KB
    const int SMEM_B = (128 * 132 + 128 * 132 + 128 * 20) * 4;   // ~142 KB
    const int SMEM_C = (128 * 132 + 128 * 132) * 4;              // ~135 KB

    cudaFuncSetAttribute(kA, cudaFuncAttributeMaxDynamicSharedMemorySize, SMEM_A);
    cudaFuncSetAttribute(kB, cudaFuncAttributeMaxDynamicSharedMemorySize, SMEM_B);
    cudaFuncSetAttribute(kC, cudaFuncAttributeMaxDynamicSharedMemorySize, SMEM_C);

    kW<<<15, 256>>>(p2a_W0, p2a_W1, p2p_W0, p2p_W1, a2p_W1, pl_W0, pl_W1,
                    al_W0, al_W1, a2a_W0, a2a_W1, a2p_W0);
    kA<<<dim3(32, 3), 256, SMEM_A>>>(atom_x, a2a_b0, a2a_b1);
    kB<<<2048, 256, SMEM_B>>>(pair_x,
                              p2a_b0, p2a_b1, p2p_b0, p2p_b1,
                              a2p_b0, a2p_b1, pl_b0, pl_b1,
                              out + ATOM_OUT);
    kC<<<32, 256, SMEM_C>>>(al_b0, al_b1, out);
}

// round 7
// speedup vs baseline: 7.7527x; 2.0740x over previous
#include <cuda_runtime.h>
#include <cuda_fp16.h>
#include <cstdint>

#define BB 64
#define NN 64
#define FA 75
#define FP 14
#define CC 128
#define NROWS_A (BB*NN)
#define ATOM_OUT (BB*NN*CC)

// ---------------- global scratch ----------------
__device__ float g_U [NROWS_A*CC];
__device__ float g_V [NROWS_A*CC];
__device__ float g_a0[NROWS_A*CC];
__device__ float g_a1[NROWS_A*CC];

// transposed ([N=128][K]) fp16, zero-padded weights
__device__ __align__(16) __half g_Wp2a0[128*16];
__device__ __align__(16) __half g_Wp2a1[128*128];
__device__ __align__(16) __half g_Wp2p0[128*16];
__device__ __align__(16) __half g_Wp2p1[128*128];
__device__ __align__(16) __half g_Wa2p1[128*128];
__device__ __align__(16) __half g_Wpl0a[128*128];
__device__ __align__(16) __half g_Wpl0b[128*128];
__device__ __align__(16) __half g_Wpl1 [128*128];
__device__ __align__(16) __half g_Wal0a[128*128];
__device__ __align__(16) __half g_Wal0b[128*128];
__device__ __align__(16) __half g_Wal1 [128*128];
__device__ __align__(16) __half g_Wa2a0 [128*80];
__device__ __align__(16) __half g_Wa2a1 [128*128];
__device__ __align__(16) __half g_Wa2p0a[128*80];
__device__ __align__(16) __half g_Wa2p0b[128*80];

// ---------------- helpers ----------------
__device__ __forceinline__ uint32_t smem_u32(const void* p){
    uint32_t a;
    asm("{ .reg .u64 t; cvta.to.shared.u64 t, %1; cvt.u32.u64 %0, t; }" : "=r"(a) : "l"(p));
    return a;
}
__device__ __forceinline__ void mma_f16(float c[4], const uint32_t a[4], const uint32_t b[2]){
    asm volatile("mma.sync.aligned.m16n8k16.row.col.f32.f16.f16.f32 "
        "{%0,%1,%2,%3}, {%4,%5,%6,%7}, {%8,%9}, {%0,%1,%2,%3};"
        : "+f"(c[0]), "+f"(c[1]), "+f"(c[2]), "+f"(c[3])
        : "r"(a[0]), "r"(a[1]), "r"(a[2]), "r"(a[3]), "r"(b[0]), "r"(b[1]));
}
__device__ __forceinline__ void zacc(float (&a)[4][4][4]){
#pragma unroll
    for (int m = 0; m < 4; ++m)
#pragma unroll
        for (int n = 0; n < 4; ++n)
#pragma unroll
            for (int q = 0; q < 4; ++q) a[m][n][q] = 0.f;
}

#define CP_COMMIT asm volatile("cp.async.commit_group;" ::: "memory")
#define CP_WAIT0  asm volatile("cp.async.wait_group 0;" ::: "memory")
#define CP_WAIT1  asm volatile("cp.async.wait_group 1;" ::: "memory")

// async copy [128][K] half gmem -> smem stride 136 halves (272B, conflict-free)
__device__ __forceinline__ void cpa_h(__half* dstS, const __half* src, int K, int tid){
    size_t gp = __cvta_generic_to_global(src);
    uint32_t base = smem_u32(dstS);
    int ch = K >> 3;                    // 16B chunks per row
    int tot = 128 * ch;
    for (int i = tid; i < tot; i += 256){
        int n = i / ch, c = i - n * ch;
        uint32_t d = base + (uint32_t)(n * 136 + c * 8) * 2u;
        asm volatile("cp.async.ca.shared.global [%0], [%1], 16;" :: "r"(d), "l"(gp + (size_t)i * 16) : "memory");
    }
    CP_COMMIT;
}

// Warp-group GEMM: 8 warps compute 128x128 += A(128xK) @ B(128xK)^T, fp16 in, fp32 acc.
template<int KSTEPS>
__device__ __forceinline__ void wg_mma(float (&acc)[4][4][4],
        const __half* __restrict__ As, int lda,
        const __half* __restrict__ Bs, int ldb,
        int wm, int wn, int lane){
    const __half* Ap = As + (wm * 64 + (lane >> 2)) * lda + ((lane & 3) << 1);
    const __half* Bp = Bs + (wn * 32 + (lane >> 2)) * ldb + ((lane & 3) << 1);
#pragma unroll
    for (int ks = 0; ks < KSTEPS; ++ks){
        const int k0 = ks * 16;
        uint32_t a[4][4], b[4][2];
#pragma unroll
        for (int mf = 0; mf < 4; ++mf){
            const __half* p = Ap + mf * 16 * lda + k0;
            a[mf][0] = *(const uint32_t*)(p);
            a[mf][1] = *(const uint32_t*)(p + 8 * lda);
            a[mf][2] = *(const uint32_t*)(p + 8);
            a[mf][3] = *(const uint32_t*)(p + 8 * lda + 8);
        }
#pragma unroll
        for (int nf = 0; nf < 4; ++nf){
            const __half* q = Bp + nf * 8 * ldb + k0;
            b[nf][0] = *(const uint32_t*)(q);
            b[nf][1] = *(const uint32_t*)(q + 8);
        }
#pragma unroll
        for (int mf = 0; mf < 4; ++mf)
#pragma unroll
            for (int nf = 0; nf < 4; ++nf)
                mma_f16(acc[mf][nf], a[mf], b[nf]);
    }
}

// relu(acc + bias) -> half smem (stride ldd halves)
__device__ __forceinline__ void epi_smem_h(const float (&acc)[4][4][4], __half* dst, int ldd,
        const float* __restrict__ bias, int wm, int wn, int lane){
    int r0 = wm * 64 + (lane >> 2);
    int c0 = wn * 32 + 2 * (lane & 3);
#pragma unroll
    for (int mf = 0; mf < 4; ++mf)
#pragma unroll
        for (int nf = 0; nf < 4; ++nf){
            int c = c0 + nf * 8;
            float bx = bias[c], by = bias[c + 1];
            int ra = r0 + mf * 16, rb = ra + 8;
            *(__half2*)(dst + ra * ldd + c) =
                __floats2half2_rn(fmaxf(acc[mf][nf][0] + bx, 0.f), fmaxf(acc[mf][nf][1] + by, 0.f));
            *(__half2*)(dst + rb * ldd + c) =
                __floats2half2_rn(fmaxf(acc[mf][nf][2] + bx, 0.f), fmaxf(acc[mf][nf][3] + by, 0.f));
        }
}

// dst += relu(acc + bias) (half smem read-modify-write)
__device__ __forceinline__ void epi_add_smem_h(const float (&acc)[4][4][4], __half* dst, int ldd,
        const float* __restrict__ bias, int wm, int wn, int lane){
    int r0 = wm * 64 + (lane >> 2);
    int c0 = wn * 32 + 2 * (lane & 3);
#pragma unroll
    for (int mf = 0; mf < 4; ++mf)
#pragma unroll
        for (int nf = 0; nf < 4; ++nf){
            int c = c0 + nf * 8;
            float bx = bias[c], by = bias[c + 1];
            int ra = r0 + mf * 16, rb = ra + 8;
            __half2* pa = (__half2*)(dst + ra * ldd + c);
            __half2* pb = (__half2*)(dst + rb * ldd + c);
            float2 oa = __half22float2(*pa), ob = __half22float2(*pb);
            *pa = __floats2half2_rn(oa.x + fmaxf(acc[mf][nf][0] + bx, 0.f),
                                    oa.y + fmaxf(acc[mf][nf][1] + by, 0.f));
            *pb = __floats2half2_rn(ob.x + fmaxf(acc[mf][nf][2] + bx, 0.f),
                                    ob.y + fmaxf(acc[mf][nf][3] + by, 0.f));
        }
}

// relu(acc + bias) -> gmem 128x128 fp32 tile
__device__ __forceinline__ void epi_gmem_relu(const float (&acc)[4][4][4], float* __restrict__ dst,
        const float* __restrict__ bias, int wm, int wn, int lane){
    int r0 = wm * 64 + (lane >> 2);
    int c0 = wn * 32 + 2 * (lane & 3);
#pragma unroll
    for (int mf = 0; mf < 4; ++mf)
#pragma unroll
        for (int nf = 0; nf < 4; ++nf){
            int c = c0 + nf * 8;
            float bx = bias[c], by = bias[c + 1];
            int ra = r0 + mf * 16, rb = ra + 8;
            *(float2*)(dst + ra * 128 + c) = make_float2(fmaxf(acc[mf][nf][0] + bx, 0.f),
                                                         fmaxf(acc[mf][nf][1] + by, 0.f));
            *(float2*)(dst + rb * 128 + c) = make_float2(fmaxf(acc[mf][nf][2] + bx, 0.f),
                                                         fmaxf(acc[mf][nf][3] + by, 0.f));
        }
}
__device__ __forceinline__ void epi_gmem_raw(const float (&acc)[4][4][4], float* __restrict__ dst,
        int wm, int wn, int lane){
    int r0 = wm * 64 + (lane >> 2);
    int c0 = wn * 32 + 2 * (lane & 3);
#pragma unroll
    for (int mf = 0; mf < 4; ++mf)
#pragma unroll
        for (int nf = 0; nf < 4; ++nf){
            int c = c0 + nf * 8;
            int ra = r0 + mf * 16, rb = ra + 8;
            *(float2*)(dst + ra * 128 + c) = make_float2(acc[mf][nf][0], acc[mf][nf][1]);
            *(float2*)(dst + rb * 128 + c) = make_float2(acc[mf][nf][2], acc[mf][nf][3]);
        }
}

// ---------------- weight prep ----------------
__device__ __forceinline__ void wprep(__half* dst, const float* src, int Kpad, int Ksrc, int tid){
    for (int i = tid; i < 128 * Kpad; i += 256){
        int n = i / Kpad, k = i - n * Kpad;
        dst[i] = __float2half_rn(k < Ksrc ? src[k * 128 + n] : 0.f);
    }
}
extern "C" __global__ void kW(const float* __restrict__ p2aW0, const float* __restrict__ p2aW1,
                              const float* __restrict__ p2pW0, const float* __restrict__ p2pW1,
                              const float* __restrict__ a2pW1, const float* __restrict__ plW0,
                              const float* __restrict__ plW1,  const float* __restrict__ alW0,
                              const float* __restrict__ alW1,  const float* __restrict__ a2aW0,
                              const float* __restrict__ a2aW1, const float* __restrict__ a2pW0){
    int t = blockIdx.x, tid = threadIdx.x;
    switch (t){
        case 0:  wprep(g_Wp2a0,  p2aW0,            16, FP,  tid); break;
        case 1:  wprep(g_Wp2a1,  p2aW1,           128, 128, tid); break;
        case 2:  wprep(g_Wp2p0,  p2pW0,            16, FP,  tid); break;
        case 3:  wprep(g_Wp2p1,  p2pW1,           128, 128, tid); break;
        case 4:  wprep(g_Wa2p1,  a2pW1,           128, 128, tid); break;
        case 5:  wprep(g_Wpl0a,  plW0,            128, 128, tid); break;
        case 6:  wprep(g_Wpl0b,  plW0 + 128*128,  128, 128, tid); break;
        case 7:  wprep(g_Wpl1,   plW1,            128, 128, tid); break;
        case 8:  wprep(g_Wal0a,  alW0,            128, 128, tid); break;
        case 9:  wprep(g_Wal0b,  alW0 + 128*128,  128, 128, tid); break;
        case 10: wprep(g_Wal1,   alW1,            128, 128, tid); break;
        case 11: wprep(g_Wa2a0,  a2aW0,            80, FA,  tid); break;
        case 12: wprep(g_Wa2a1,  a2aW1,           128, 128, tid); break;
        case 13: wprep(g_Wa2p0a, a2pW0,            80, FA,  tid); break;
        default: wprep(g_Wa2p0b, a2pW0 + FA*128,   80, FA,  tid); break;
    }
}

// ---------------- kernel A: atom precompute ----------------
// grid (32,3): blk = 2 batches (128 rows). task 0: a0=MLP2(atom;a2a)->g_a0,
// task 1: U=atom@a2pW0[:75], task 2: V=atom@a2pW0[75:]
extern "C" __global__ void __launch_bounds__(256, 1)
kA(const float* __restrict__ atom_x,
   const float* __restrict__ a2a_b0, const float* __restrict__ a2a_b1){
    extern __shared__ __half smh[];
    __half* As  = smh;                    // 128*88
    __half* act = As + 128 * 88;          // 128*136
    __half* Bw  = act + 128 * 136;        // 128*136
    int tid = threadIdx.x, lane = tid & 31, w = tid >> 5;
    int wm = w & 1, wn = w >> 1;
    int blk = blockIdx.x, task = blockIdx.y;

    const __half* w0 = (task == 0) ? g_Wa2a0 : (task == 1 ? g_Wa2p0a : g_Wa2p0b);
    cpa_h(Bw, w0, 80, tid);
    for (int i = tid; i < 128 * 80; i += 256){
        int r = i / 80, k = i - r * 80;
        float v = (k < FA) ? atom_x[(blk * 128 + r) * FA + k] : 0.f;
        As[r * 88 + k] = __float2half_rn(v);
    }
    CP_WAIT0;
    __syncthreads();

    float acc[4][4][4];
    zacc(acc);
    wg_mma<5>(acc, As, 88, Bw, 136, wm, wn, lane);
    if (task == 0){
        __syncthreads();
        cpa_h(Bw, g_Wa2a1, 128, tid);
        epi_smem_h(acc, act, 136, a2a_b0, wm, wn, lane);
        CP_WAIT0;
        __syncthreads();
        zacc(acc);
        wg_mma<8>(acc, act, 136, Bw, 136, wm, wn, lane);
        epi_gmem_relu(acc, g_a0 + blk * 16384, a2a_b1, wm, wn, lane);
    } else {
        float* dst = (task == 1 ? g_U : g_V) + blk * 16384;
        epi_gmem_raw(acc, dst, wm, wn, lane);
    }
}

// ---------------- kernel B: fused pair pipeline (fp16 mma, 9 GEMMs, 1 acc) ----------------
// grid 2048: CTA per (b,i2); rows r: ih = 2*i2 + (r>>6), j = r&63.
// smem halves: actA 128*136 | actB 128*136 | Bw 128*136 | pxs 128*24  (=108 KB, 2 CTAs/SM)
extern "C" __global__ void __launch_bounds__(256, 2)
kB(const float* __restrict__ pair_x,
   const float* __restrict__ p2a_b0, const float* __restrict__ p2a_b1,
   const float* __restrict__ p2p_b0, const float* __restrict__ p2p_b1,
   const float* __restrict__ a2p_b0, const float* __restrict__ a2p_b1,
   const float* __restrict__ pl_b0,  const float* __restrict__ pl_b1,
   float* __restrict__ out_pair){
    extern __shared__ __half smh[];
    __half* actA = smh;                   // 128*136
    __half* actB = actA + 128 * 136;      // 128*136
    __half* Bw   = actB + 128 * 136;      // 128*136
    __half* pxs  = Bw + 128 * 136;        // 128*24
    int tid = threadIdx.x, lane = tid & 31, w = tid >> 5;
    int wm = w & 1, wn = w >> 1;
    int cta = blockIdx.x;
    int b = cta >> 5, i2 = cta & 31;
    size_t tilebase = (size_t)b * 4096 + (size_t)i2 * 128;
    const float* gU = g_U + b * 8192;
    const float* gV = g_V + b * 8192;

    float acc[4][4][4];

    // ---- prologue: p2a W0 + pxs ----
    cpa_h(Bw, g_Wp2a0, 16, tid);
    for (int i = tid; i < 128 * 16; i += 256){
        int r = i >> 4, k = i & 15;
        float v = (k < FP) ? pair_x[(tilebase + r) * FP + k] : 0.f;
        pxs[r * 24 + k] = __float2half_rn(v);
    }
    CP_WAIT0;
    __syncthreads();

    // ---- G1: px @ p2aW0 ----
    zacc(acc);
    wg_mma<1>(acc, pxs, 24, Bw, 136, wm, wn, lane);
    __syncthreads();
    cpa_h(Bw, g_Wp2a1, 128, tid);
    epi_smem_h(acc, actA, 136, p2a_b0, wm, wn, lane);
    CP_WAIT0;
    __syncthreads();

    // ---- G2: actA @ p2aW1 ; epi = relu + column-sum -> g_a1 ; build h0 -> actA ----
    zacc(acc);
    wg_mma<8>(acc, actA, 136, Bw, 136, wm, wn, lane);
    __syncthreads();
    cpa_h(Bw, g_Wa2p1, 128, tid);
    {
        int c0 = wn * 32 + 2 * (lane & 3);
#pragma unroll
        for (int nf = 0; nf < 4; ++nf){
            int c = c0 + nf * 8;
            float bx = p2a_b1[c], by = p2a_b1[c + 1];
            float s0 = 0.f, s1 = 0.f;
#pragma unroll
            for (int mf = 0; mf < 4; ++mf){
                s0 += fmaxf(acc[mf][nf][0] + bx, 0.f) + fmaxf(acc[mf][nf][2] + bx, 0.f);
                s1 += fmaxf(acc[mf][nf][1] + by, 0.f) + fmaxf(acc[mf][nf][3] + by, 0.f);
            }
#pragma unroll
            for (int off = 4; off < 32; off <<= 1){
                s0 += __shfl_xor_sync(0xFFFFFFFFu, s0, off);
                s1 += __shfl_xor_sync(0xFFFFFFFFu, s1, off);
            }
            if (lane < 4){
                float* gr = g_a1 + ((size_t)b * 64 + i2 * 2 + wm) * 128 + c;
                gr[0] = s0; gr[1] = s1;
            }
        }
    }
    for (int i = tid; i < 128 * 32; i += 256){      // h0 = relu(U[ih] + V[j] + b0a)
        int r = i >> 5, c4 = (i & 31) << 2;
        int ih = i2 * 2 + (r >> 6), j = r & 63;
        float4 uu = *(const float4*)(gU + ih * 128 + c4);
        float4 vv = *(const float4*)(gV + j  * 128 + c4);
        float4 bb = *(const float4*)(a2p_b0 + c4);
        *(__half2*)(actA + r * 136 + c4)     = __floats2half2_rn(fmaxf(uu.x + vv.x + bb.x, 0.f),
                                                                 fmaxf(uu.y + vv.y + bb.y, 0.f));
        *(__half2*)(actA + r * 136 + c4 + 2) = __floats2half2_rn(fmaxf(uu.z + vv.z + bb.z, 0.f),
                                                                 fmaxf(uu.w + vv.w + bb.w, 0.f));
    }
    CP_WAIT0;
    __syncthreads();

    // ---- G3: h0 @ a2pW1 (y0) ; epi relu -> actB ; build h1 -> actA ----
    zacc(acc);
    wg_mma<8>(acc, actA, 136, Bw, 136, wm, wn, lane);
    __syncthreads();
    epi_smem_h(acc, actB, 136, a2p_b1, wm, wn, lane);
    for (int i = tid; i < 128 * 32; i += 256){      // h1 = relu(U[j] + V[ih] + b0a)
        int r = i >> 5, c4 = (i & 31) << 2;
        int ih = i2 * 2 + (r >> 6), j = r & 63;
        float4 uu = *(const float4*)(gU + j  * 128 + c4);
        float4 vv = *(const float4*)(gV + ih * 128 + c4);
        float4 bb = *(const float4*)(a2p_b0 + c4);
        *(__half2*)(actA + r * 136 + c4)     = __floats2half2_rn(fmaxf(uu.x + vv.x + bb.x, 0.f),
                                                                 fmaxf(uu.y + vv.y + bb.y, 0.f));
        *(__half2*)(actA + r * 136 + c4 + 2) = __floats2half2_rn(fmaxf(uu.z + vv.z + bb.z, 0.f),
                                                                 fmaxf(uu.w + vv.w + bb.w, 0.f));
    }
    __syncthreads();    // Bw still holds a2pW1 — reused

    // ---- G4: h1 @ a2pW1 (y1) ; epi: actB += relu -> actB = p0 ----
    zacc(acc);
    wg_mma<8>(acc, actA, 136, Bw, 136, wm, wn, lane);
    __syncthreads();
    cpa_h(Bw, g_Wp2p0, 16, tid);
    epi_add_smem_h(acc, actB, 136, a2p_b1, wm, wn, lane);
    CP_WAIT0;
    __syncthreads();

    // ---- G5: px @ p2pW0 ----
    zacc(acc);
    wg_mma<1>(acc, pxs, 24, Bw, 136, wm, wn, lane);
    __syncthreads();
    cpa_h(Bw, g_Wp2p1, 128, tid);
    epi_smem_h(acc, actA, 136, p2p_b0, wm, wn, lane);
    CP_WAIT0;
    __syncthreads();

    // ---- G6: actA @ p2pW1 ; epi relu -> actA = p1 ----
    zacc(acc);
    wg_mma<8>(acc, actA, 136, Bw, 136, wm, wn, lane);
    __syncthreads();
    cpa_h(Bw, g_Wpl0b, 128, tid);
    epi_smem_h(acc, actA, 136, p2p_b1, wm, wn, lane);
    CP_WAIT0;
    __syncthreads();

    // ---- G7: p1 @ plW0b (no epilogue) ----
    zacc(acc);
    wg_mma<8>(acc, actA, 136, Bw, 136, wm, wn, lane);
    __syncthreads();
    cpa_h(Bw, g_Wpl0a, 128, tid);
    CP_WAIT0;
    __syncthreads();

    // ---- G8: acc += p0 @ plW0a ; epi relu -> actA ----
    wg_mma<8>(acc, actB, 136, Bw, 136, wm, wn, lane);
    __syncthreads();
    cpa_h(Bw, g_Wpl1, 128, tid);
    epi_smem_h(acc, actA, 136, pl_b0, wm, wn, lane);
    CP_WAIT0;
    __syncthreads();

    // ---- G9: actA @ plW1 -> out ----
    zacc(acc);
    wg_mma<8>(acc, actA, 136, Bw, 136, wm, wn, lane);
    epi_gmem_relu(acc, out_pair + tilebase * 128, pl_b1, wm, wn, lane);
}

// ---------------- kernel C: atom finalize ----------------
// grid 32: blk = 2 batches (128 rows). smem halves: As 128*136 | Bw0 | Bw1
extern "C" __global__ void __launch_bounds__(256, 1)
kC(const float* __restrict__ al_b0, const float* __restrict__ al_b1,
   float* __restrict__ out_atom){
    extern __shared__ __half smh[];
    __half* As  = smh;                    // 128*136
    __half* Bw0 = As + 128 * 136;
    __half* Bw1 = Bw0 + 128 * 136;
    int tid = threadIdx.x, lane = tid & 31, w = tid >> 5;
    int wm = w & 1, wn = w >> 1;
    int blk = blockIdx.x;

    cpa_h(Bw0, g_Wal0a, 128, tid);
    cpa_h(Bw1, g_Wal0b, 128, tid);
    for (int i = tid; i < 128 * 32; i += 256){
        int r = i >> 5, c4 = (i & 31) << 2;
        float4 v = *(const float4*)(g_a0 + blk * 16384 + r * 128 + c4);
        *(__half2*)(As + r * 136 + c4)     = __floats2half2_rn(v.x, v.y);
        *(__half2*)(As + r * 136 + c4 + 2) = __floats2half2_rn(v.z, v.w);
    }
    CP_WAIT1;
    __syncthreads();

    float acc[4][4][4];
    zacc(acc);
    wg_mma<8>(acc, As, 136, Bw0, 136, wm, wn, lane);
    __syncthreads();
    cpa_h(Bw0, g_Wal1, 128, tid);
    for (int i = tid; i < 128 * 32; i += 256){
        int r = i >> 5, c4 = (i & 31) << 2;
        float4 v = *(const float4*)(g_a1 + blk * 16384 + r * 128 + c4);
        *(__half2*)(As + r * 136 + c4)     = __floats2half2_rn(v.x, v.y);
        *(__half2*)(As + r * 136 + c4 + 2) = __floats2half2_rn(v.z, v.w);
    }
    CP_WAIT1;                               // Bw1 ready
    __syncthreads();

    wg_mma<8>(acc, As, 136, Bw1, 136, wm, wn, lane);
    __syncthreads();
    epi_smem_h(acc, As, 136, al_b0, wm, wn, lane);
    CP_WAIT0;                               // Bw0 = al1 ready
    __syncthreads();

    zacc(acc);
    wg_mma<8>(acc, As, 136, Bw0, 136, wm, wn, lane);
    epi_gmem_relu(acc, out_atom + blk * 16384, al_b1, wm, wn, lane);
}

// ---------------------------------------------------------------------------
extern "C" void kernel_launch(void* const* d_in, const int* in_sizes, int n_in,
                              void* d_out, int out_size) {
    const float* atom_x = (const float*)d_in[0];
    const float* pair_x = (const float*)d_in[1];
    const float* a2a_W0 = (const float*)d_in[2];
    const float* a2a_b0 = (const float*)d_in[3];
    const float* a2a_W1 = (const float*)d_in[4];
    const float* a2a_b1 = (const float*)d_in[5];
    const float* p2a_W0 = (const float*)d_in[6];
    const float* p2a_b0 = (const float*)d_in[7];
    const float* p2a_W1 = (const float*)d_in[8];
    const float* p2a_b1 = (const float*)d_in[9];
    const float* al_W0  = (const float*)d_in[10];
    const float* al_b0  = (const float*)d_in[11];
    const float* al_W1  = (const float*)d_in[12];
    const float* al_b1  = (const float*)d_in[13];
    const float* a2p_W0 = (const float*)d_in[14];
    const float* a2p_b0 = (const float*)d_in[15];
    const float* a2p_W1 = (const float*)d_in[16];
    const float* a2p_b1 = (const float*)d_in[17];
    const float* p2p_W0 = (const float*)d_in[18];
    const float* p2p_b0 = (const float*)d_in[19];
    const float* p2p_W1 = (const float*)d_in[20];
    const float* p2p_b1 = (const float*)d_in[21];
    const float* pl_W0  = (const float*)d_in[22];
    const float* pl_b0  = (const float*)d_in[23];
    const float* pl_W1  = (const float*)d_in[24];
    const float* pl_b1  = (const float*)d_in[25];
    float* out = (float*)d_out;

    const int SMEM_A = (128 * 88 + 128 * 136 + 128 * 136) * 2;           // 92160 B
    const int SMEM_B = (3 * 128 * 136 + 128 * 24) * 2;                   // 110592 B
    const int SMEM_C = (3 * 128 * 136) * 2;                              // 104448 B

    cudaFuncSetAttribute(kA, cudaFuncAttributeMaxDynamicSharedMemorySize, SMEM_A);
    cudaFuncSetAttribute(kB, cudaFuncAttributeMaxDynamicSharedMemorySize, SMEM_B);
    cudaFuncSetAttribute(kC, cudaFuncAttributeMaxDynamicSharedMemorySize, SMEM_C);

    kW<<<15, 256>>>(p2a_W0, p2a_W1, p2p_W0, p2p_W1, a2p_W1, pl_W0, pl_W1,
                    al_W0, al_W1, a2a_W0, a2a_W1, a2p_W0);
    kA<<<dim3(32, 3), 256, SMEM_A>>>(atom_x, a2a_b0, a2a_b1);
    kB<<<2048, 256, SMEM_B>>>(pair_x,
                              p2a_b0, p2a_b1, p2p_b0, p2p_b1,
                              a2p_b0, a2p_b1, pl_b0, pl_b1,
                              out + ATOM_OUT);
    kC<<<32, 256, SMEM_C>>>(al_b0, al_b1, out);
}

// round 8
// speedup vs baseline: 8.3651x; 1.0790x over previous
#include <cuda_runtime.h>
#include <cuda_fp16.h>
#include <cstdint>

#define BB 64
#define NN 64
#define FA 75
#define FP 14
#define CC 128
#define NROWS_A (BB*NN)
#define ATOM_OUT (BB*NN*CC)

// ---------------- global scratch ----------------
__device__ float g_U [NROWS_A*CC];
__device__ float g_V [NROWS_A*CC];
__device__ float g_a0[NROWS_A*CC];
__device__ float g_a1[NROWS_A*CC];

// transposed ([N=128][K]) fp16, zero-padded weights
__device__ __align__(16) __half g_Wp2a0[128*16];
__device__ __align__(16) __half g_Wp2a1[128*128];
__device__ __align__(16) __half g_Wp2p0[128*16];
__device__ __align__(16) __half g_Wp2p1[128*128];
__device__ __align__(16) __half g_Wa2p1[128*128];
__device__ __align__(16) __half g_Wpl0a[128*128];
__device__ __align__(16) __half g_Wpl0b[128*128];
__device__ __align__(16) __half g_Wpl1 [128*128];
__device__ __align__(16) __half g_Wal0a[128*128];
__device__ __align__(16) __half g_Wal0b[128*128];
__device__ __align__(16) __half g_Wal1 [128*128];
__device__ __align__(16) __half g_Wa2a0 [128*80];
__device__ __align__(16) __half g_Wa2a1 [128*128];
__device__ __align__(16) __half g_Wa2p0a[128*80];
__device__ __align__(16) __half g_Wa2p0b[128*80];

// ---------------- helpers ----------------
__device__ __forceinline__ uint32_t smem_u32(const void* p){
    uint32_t a;
    asm("{ .reg .u64 t; cvta.to.shared.u64 t, %1; cvt.u32.u64 %0, t; }" : "=r"(a) : "l"(p));
    return a;
}
__device__ __forceinline__ void mma_f16(float c[4], const uint32_t a[4], const uint32_t b[2]){
    asm volatile("mma.sync.aligned.m16n8k16.row.col.f32.f16.f16.f32 "
        "{%0,%1,%2,%3}, {%4,%5,%6,%7}, {%8,%9}, {%0,%1,%2,%3};"
        : "+f"(c[0]), "+f"(c[1]), "+f"(c[2]), "+f"(c[3])
        : "r"(a[0]), "r"(a[1]), "r"(a[2]), "r"(a[3]), "r"(b[0]), "r"(b[1]));
}
__device__ __forceinline__ void ldsm4(uint32_t* r, uint32_t addr){
    asm volatile("ldmatrix.sync.aligned.m8n8.x4.shared.b16 {%0,%1,%2,%3}, [%4];"
        : "=r"(r[0]), "=r"(r[1]), "=r"(r[2]), "=r"(r[3]) : "r"(addr));
}

#define CP_COMMIT asm volatile("cp.async.commit_group;" ::: "memory")
#define CP_WAIT0  asm volatile("cp.async.wait_group 0;" ::: "memory")
#define CP_WAIT1  asm volatile("cp.async.wait_group 1;" ::: "memory")

// async copy [128][K] half gmem -> smem stride 136 halves (272B, conflict-free)
__device__ __forceinline__ void cpa_h(__half* dstS, const __half* src, int K, int tid){
    size_t gp = __cvta_generic_to_global(src);
    uint32_t base = smem_u32(dstS);
    int ch = K >> 3;                    // 16B chunks per row
    int tot = 128 * ch;
    for (int i = tid; i < tot; i += 256){
        int n = i / ch, c = i - n * ch;
        uint32_t d = base + (uint32_t)(n * 136 + c * 8) * 2u;
        asm volatile("cp.async.ca.shared.global [%0], [%1], 16;" :: "r"(d), "l"(gp + (size_t)i * 16) : "memory");
    }
    CP_COMMIT;
}

// ---- LDSM warp GEMM: warp tile (MF*16) x (NF*8), both operands stride 136 halves ----
template<int KSTEPS, int MF, int NF>
__device__ __forceinline__ void wg_ldsm(float (&acc)[MF][NF][4],
        uint32_t Asa, uint32_t Bsa, int wrow, int wcol, int lane){
    const int t = lane >> 3, tr = lane & 7;
    uint32_t aA[MF], aB[NF/2];
#pragma unroll
    for (int mf = 0; mf < MF; ++mf)
        aA[mf] = Asa + (uint32_t)((wrow + mf * 16 + (t & 1) * 8 + tr) * 136 + (t >> 1) * 8) * 2u;
#pragma unroll
    for (int p = 0; p < NF / 2; ++p)
        aB[p] = Bsa + (uint32_t)((wcol + (2 * p + (t >> 1)) * 8 + tr) * 136 + (t & 1) * 8) * 2u;
#pragma unroll
    for (int ks = 0; ks < KSTEPS; ++ks){
        uint32_t a[MF][4], b[NF][2];
#pragma unroll
        for (int mf = 0; mf < MF; ++mf) ldsm4(a[mf], aA[mf] + ks * 32);
#pragma unroll
        for (int p = 0; p < NF / 2; ++p) ldsm4(&b[2 * p][0], aB[p] + ks * 32);
#pragma unroll
        for (int mf = 0; mf < MF; ++mf)
#pragma unroll
            for (int nf = 0; nf < NF; ++nf)
                mma_f16(acc[mf][nf], a[mf], b[nf]);
    }
}

// ---- legacy LDS warp GEMM (for K=16 pxs GEMMs, lda=24) ----
template<int KSTEPS>
__device__ __forceinline__ void wg_mma(float (&acc)[4][4][4],
        const __half* __restrict__ As, int lda,
        const __half* __restrict__ Bs, int ldb,
        int wm, int wn, int lane){
    const __half* Ap = As + (wm * 64 + (lane >> 2)) * lda + ((lane & 3) << 1);
    const __half* Bp = Bs + (wn * 32 + (lane >> 2)) * ldb + ((lane & 3) << 1);
#pragma unroll
    for (int ks = 0; ks < KSTEPS; ++ks){
        const int k0 = ks * 16;
        uint32_t a[4][4], b[4][2];
#pragma unroll
        for (int mf = 0; mf < 4; ++mf){
            const __half* p = Ap + mf * 16 * lda + k0;
            a[mf][0] = *(const uint32_t*)(p);
            a[mf][1] = *(const uint32_t*)(p + 8 * lda);
            a[mf][2] = *(const uint32_t*)(p + 8);
            a[mf][3] = *(const uint32_t*)(p + 8 * lda + 8);
        }
#pragma unroll
        for (int nf = 0; nf < 4; ++nf){
            const __half* q = Bp + nf * 8 * ldb + k0;
            b[nf][0] = *(const uint32_t*)(q);
            b[nf][1] = *(const uint32_t*)(q + 8);
        }
#pragma unroll
        for (int mf = 0; mf < 4; ++mf)
#pragma unroll
            for (int nf = 0; nf < 4; ++nf)
                mma_f16(acc[mf][nf], a[mf], b[nf]);
    }
}

__device__ __forceinline__ void zacc(float (&a)[4][4][4]){
#pragma unroll
    for (int m = 0; m < 4; ++m)
#pragma unroll
        for (int n = 0; n < 4; ++n)
#pragma unroll
            for (int q = 0; q < 4; ++q) a[m][n][q] = 0.f;
}

// relu(acc + bias) -> half smem (stride ldd halves)
__device__ __forceinline__ void epi_smem_h(const float (&acc)[4][4][4], __half* dst, int ldd,
        const float* __restrict__ bias, int wm, int wn, int lane){
    int r0 = wm * 64 + (lane >> 2);
    int c0 = wn * 32 + 2 * (lane & 3);
#pragma unroll
    for (int mf = 0; mf < 4; ++mf)
#pragma unroll
        for (int nf = 0; nf < 4; ++nf){
            int c = c0 + nf * 8;
            float bx = bias[c], by = bias[c + 1];
            int ra = r0 + mf * 16, rb = ra + 8;
            *(__half2*)(dst + ra * ldd + c) =
                __floats2half2_rn(fmaxf(acc[mf][nf][0] + bx, 0.f), fmaxf(acc[mf][nf][1] + by, 0.f));
            *(__half2*)(dst + rb * ldd + c) =
                __floats2half2_rn(fmaxf(acc[mf][nf][2] + bx, 0.f), fmaxf(acc[mf][nf][3] + by, 0.f));
        }
}

// dst += relu(acc + bias)
__device__ __forceinline__ void epi_add_smem_h(const float (&acc)[4][4][4], __half* dst, int ldd,
        const float* __restrict__ bias, int wm, int wn, int lane){
    int r0 = wm * 64 + (lane >> 2);
    int c0 = wn * 32 + 2 * (lane & 3);
#pragma unroll
    for (int mf = 0; mf < 4; ++mf)
#pragma unroll
        for (int nf = 0; nf < 4; ++nf){
            int c = c0 + nf * 8;
            float bx = bias[c], by = bias[c + 1];
            int ra = r0 + mf * 16, rb = ra + 8;
            __half2* pa = (__half2*)(dst + ra * ldd + c);
            __half2* pb = (__half2*)(dst + rb * ldd + c);
            float2 oa = __half22float2(*pa), ob = __half22float2(*pb);
            *pa = __floats2half2_rn(oa.x + fmaxf(acc[mf][nf][0] + bx, 0.f),
                                    oa.y + fmaxf(acc[mf][nf][1] + by, 0.f));
            *pb = __floats2half2_rn(ob.x + fmaxf(acc[mf][nf][2] + bx, 0.f),
                                    ob.y + fmaxf(acc[mf][nf][3] + by, 0.f));
        }
}

// relu(acc + bias) -> gmem 128x128 fp32 tile
__device__ __forceinline__ void epi_gmem_relu(const float (&acc)[4][4][4], float* __restrict__ dst,
        const float* __restrict__ bias, int wm, int wn, int lane){
    int r0 = wm * 64 + (lane >> 2);
    int c0 = wn * 32 + 2 * (lane & 3);
#pragma unroll
    for (int mf = 0; mf < 4; ++mf)
#pragma unroll
        for (int nf = 0; nf < 4; ++nf){
            int c = c0 + nf * 8;
            float bx = bias[c], by = bias[c + 1];
            int ra = r0 + mf * 16, rb = ra + 8;
            *(float2*)(dst + ra * 128 + c) = make_float2(fmaxf(acc[mf][nf][0] + bx, 0.f),
                                                         fmaxf(acc[mf][nf][1] + by, 0.f));
            *(float2*)(dst + rb * 128 + c) = make_float2(fmaxf(acc[mf][nf][2] + bx, 0.f),
                                                         fmaxf(acc[mf][nf][3] + by, 0.f));
        }
}
__device__ __forceinline__ void epi_gmem_raw(const float (&acc)[4][4][4], float* __restrict__ dst,
        int wm, int wn, int lane){
    int r0 = wm * 64 + (lane >> 2);
    int c0 = wn * 32 + 2 * (lane & 3);
#pragma unroll
    for (int mf = 0; mf < 4; ++mf)
#pragma unroll
        for (int nf = 0; nf < 4; ++nf){
            int c = c0 + nf * 8;
            int ra = r0 + mf * 16, rb = ra + 8;
            *(float2*)(dst + ra * 128 + c) = make_float2(acc[mf][nf][0], acc[mf][nf][1]);
            *(float2*)(dst + rb * 128 + c) = make_float2(acc[mf][nf][2], acc[mf][nf][3]);
        }
}

// ---------------- weight prep ----------------
__device__ __forceinline__ void wprep(__half* dst, const float* src, int Kpad, int Ksrc, int tid){
    for (int i = tid; i < 128 * Kpad; i += 256){
        int n = i / Kpad, k = i - n * Kpad;
        dst[i] = __float2half_rn(k < Ksrc ? src[k * 128 + n] : 0.f);
    }
}
extern "C" __global__ void kW(const float* __restrict__ p2aW0, const float* __restrict__ p2aW1,
                              const float* __restrict__ p2pW0, const float* __restrict__ p2pW1,
                              const float* __restrict__ a2pW1, const float* __restrict__ plW0,
                              const float* __restrict__ plW1,  const float* __restrict__ alW0,
                              const float* __restrict__ alW1,  const float* __restrict__ a2aW0,
                              const float* __restrict__ a2aW1, const float* __restrict__ a2pW0){
    int t = blockIdx.x, tid = threadIdx.x;
    switch (t){
        case 0:  wprep(g_Wp2a0,  p2aW0,            16, FP,  tid); break;
        case 1:  wprep(g_Wp2a1,  p2aW1,           128, 128, tid); break;
        case 2:  wprep(g_Wp2p0,  p2pW0,            16, FP,  tid); break;
        case 3:  wprep(g_Wp2p1,  p2pW1,           128, 128, tid); break;
        case 4:  wprep(g_Wa2p1,  a2pW1,           128, 128, tid); break;
        case 5:  wprep(g_Wpl0a,  plW0,            128, 128, tid); break;
        case 6:  wprep(g_Wpl0b,  plW0 + 128*128,  128, 128, tid); break;
        case 7:  wprep(g_Wpl1,   plW1,            128, 128, tid); break;
        case 8:  wprep(g_Wal0a,  alW0,            128, 128, tid); break;
        case 9:  wprep(g_Wal0b,  alW0 + 128*128,  128, 128, tid); break;
        case 10: wprep(g_Wal1,   alW1,            128, 128, tid); break;
        case 11: wprep(g_Wa2a0,  a2aW0,            80, FA,  tid); break;
        case 12: wprep(g_Wa2a1,  a2aW1,           128, 128, tid); break;
        case 13: wprep(g_Wa2p0a, a2pW0,            80, FA,  tid); break;
        default: wprep(g_Wa2p0b, a2pW0 + FA*128,   80, FA,  tid); break;
    }
}

// ---------------- kernel A: atom precompute ----------------
// grid (32,3): blk = 2 batches (128 rows). task 0: a0=MLP2(atom;a2a)->g_a0,
// task 1: U=atom@a2pW0[:75], task 2: V=atom@a2pW0[75:]
extern "C" __global__ void __launch_bounds__(256, 1)
kA(const float* __restrict__ atom_x,
   const float* __restrict__ a2a_b0, const float* __restrict__ a2a_b1){
    extern __shared__ __half smh[];
    __half* As  = smh;                    // 128*136
    __half* act = As + 128 * 136;         // 128*136
    __half* Bw  = act + 128 * 136;        // 128*136
    int tid = threadIdx.x, lane = tid & 31, w = tid >> 5;
    int wm = w & 1, wn = w >> 1;
    int blk = blockIdx.x, task = blockIdx.y;
    uint32_t As_a = smem_u32(As), act_a = smem_u32(act), Bw_a = smem_u32(Bw);

    const __half* w0 = (task == 0) ? g_Wa2a0 : (task == 1 ? g_Wa2p0a : g_Wa2p0b);
    cpa_h(Bw, w0, 80, tid);
    for (int i = tid; i < 128 * 80; i += 256){
        int r = i / 80, k = i - r * 80;
        float v = (k < FA) ? atom_x[(blk * 128 + r) * FA + k] : 0.f;
        As[r * 136 + k] = __float2half_rn(v);
    }
    CP_WAIT0;
    __syncthreads();

    float acc[4][4][4];
    zacc(acc);
    wg_ldsm<5, 4, 4>(acc, As_a, Bw_a, wm * 64, wn * 32, lane);
    if (task == 0){
        __syncthreads();
        cpa_h(Bw, g_Wa2a1, 128, tid);
        epi_smem_h(acc, act, 136, a2a_b0, wm, wn, lane);
        CP_WAIT0;
        __syncthreads();
        zacc(acc);
        wg_ldsm<8, 4, 4>(acc, act_a, Bw_a, wm * 64, wn * 32, lane);
        epi_gmem_relu(acc, g_a0 + blk * 16384, a2a_b1, wm, wn, lane);
    } else {
        float* dst = (task == 1 ? g_U : g_V) + blk * 16384;
        epi_gmem_raw(acc, dst, wm, wn, lane);
    }
}

// ---------------- kernel B: fused pair pipeline (fp16 mma + LDSM, 9 GEMMs) ----------------
// grid 2048: CTA per (b,i2); rows r: ih = 2*i2 + (r>>6), j = r&63.
// smem halves: actA 128*136 | actB 128*136 | Bw 128*136 | pxs 128*24  (=108 KB, 2 CTAs/SM)
extern "C" __global__ void __launch_bounds__(256, 2)
kB(const float* __restrict__ pair_x,
   const float* __restrict__ p2a_b0, const float* __restrict__ p2a_b1,
   const float* __restrict__ p2p_b0, const float* __restrict__ p2p_b1,
   const float* __restrict__ a2p_b0, const float* __restrict__ a2p_b1,
   const float* __restrict__ pl_b0,  const float* __restrict__ pl_b1,
   float* __restrict__ out_pair){
    extern __shared__ __half smh[];
    __half* actA = smh;                   // 128*136
    __half* actB = actA + 128 * 136;      // 128*136
    __half* Bw   = actB + 128 * 136;      // 128*136
    __half* pxs  = Bw + 128 * 136;        // 128*24
    int tid = threadIdx.x, lane = tid & 31, w = tid >> 5;
    int wm = w & 1, wn = w >> 1;
    int cta = blockIdx.x;
    int b = cta >> 5, i2 = cta & 31;
    size_t tilebase = (size_t)b * 4096 + (size_t)i2 * 128;
    const float* gU = g_U + b * 8192;
    const float* gV = g_V + b * 8192;
    uint32_t actA_a = smem_u32(actA), actB_a = smem_u32(actB), Bw_a = smem_u32(Bw);
    const int wr = wm * 64, wc = wn * 32;

    float acc[4][4][4];

    // ---- prologue: p2a W0 + pxs ----
    cpa_h(Bw, g_Wp2a0, 16, tid);
    for (int i = tid; i < 128 * 16; i += 256){
        int r = i >> 4, k = i & 15;
        float v = (k < FP) ? pair_x[(tilebase + r) * FP + k] : 0.f;
        pxs[r * 24 + k] = __float2half_rn(v);
    }
    CP_WAIT0;
    __syncthreads();

    // ---- G1: px @ p2aW0 ----
    zacc(acc);
    wg_mma<1>(acc, pxs, 24, Bw, 136, wm, wn, lane);
    __syncthreads();
    cpa_h(Bw, g_Wp2a1, 128, tid);
    epi_smem_h(acc, actA, 136, p2a_b0, wm, wn, lane);
    CP_WAIT0;
    __syncthreads();

    // ---- G2: actA @ p2aW1 ; epi = relu + column-sum -> g_a1 ; build h0 -> actA ----
    zacc(acc);
    wg_ldsm<8, 4, 4>(acc, actA_a, Bw_a, wr, wc, lane);
    __syncthreads();
    cpa_h(Bw, g_Wa2p1, 128, tid);
    {
        int c0 = wc + 2 * (lane & 3);
#pragma unroll
        for (int nf = 0; nf < 4; ++nf){
            int c = c0 + nf * 8;
            float bx = p2a_b1[c], by = p2a_b1[c + 1];
            float s0 = 0.f, s1 = 0.f;
#pragma unroll
            for (int mf = 0; mf < 4; ++mf){
                s0 += fmaxf(acc[mf][nf][0] + bx, 0.f) + fmaxf(acc[mf][nf][2] + bx, 0.f);
                s1 += fmaxf(acc[mf][nf][1] + by, 0.f) + fmaxf(acc[mf][nf][3] + by, 0.f);
            }
#pragma unroll
            for (int off = 4; off < 32; off <<= 1){
                s0 += __shfl_xor_sync(0xFFFFFFFFu, s0, off);
                s1 += __shfl_xor_sync(0xFFFFFFFFu, s1, off);
            }
            if (lane < 4){
                float* gr = g_a1 + ((size_t)b * 64 + i2 * 2 + wm) * 128 + c;
                gr[0] = s0; gr[1] = s1;
            }
        }
    }
    for (int i = tid; i < 128 * 32; i += 256){      // h0 = relu(U[ih] + V[j] + b0a)
        int r = i >> 5, c4 = (i & 31) << 2;
        int ih = i2 * 2 + (r >> 6), j = r & 63;
        float4 uu = *(const float4*)(gU + ih * 128 + c4);
        float4 vv = *(const float4*)(gV + j  * 128 + c4);
        float4 bb = *(const float4*)(a2p_b0 + c4);
        *(__half2*)(actA + r * 136 + c4)     = __floats2half2_rn(fmaxf(uu.x + vv.x + bb.x, 0.f),
                                                                 fmaxf(uu.y + vv.y + bb.y, 0.f));
        *(__half2*)(actA + r * 136 + c4 + 2) = __floats2half2_rn(fmaxf(uu.z + vv.z + bb.z, 0.f),
                                                                 fmaxf(uu.w + vv.w + bb.w, 0.f));
    }
    CP_WAIT0;
    __syncthreads();

    // ---- G3: h0 @ a2pW1 (y0) ; epi relu -> actB ; build h1 -> actA ----
    zacc(acc);
    wg_ldsm<8, 4, 4>(acc, actA_a, Bw_a, wr, wc, lane);
    __syncthreads();
    epi_smem_h(acc, actB, 136, a2p_b1, wm, wn, lane);
    for (int i = tid; i < 128 * 32; i += 256){      // h1 = relu(U[j] + V[ih] + b0a)
        int r = i >> 5, c4 = (i & 31) << 2;
        int ih = i2 * 2 + (r >> 6), j = r & 63;
        float4 uu = *(const float4*)(gU + j  * 128 + c4);
        float4 vv = *(const float4*)(gV + ih * 128 + c4);
        float4 bb = *(const float4*)(a2p_b0 + c4);
        *(__half2*)(actA + r * 136 + c4)     = __floats2half2_rn(fmaxf(uu.x + vv.x + bb.x, 0.f),
                                                                 fmaxf(uu.y + vv.y + bb.y, 0.f));
        *(__half2*)(actA + r * 136 + c4 + 2) = __floats2half2_rn(fmaxf(uu.z + vv.z + bb.z, 0.f),
                                                                 fmaxf(uu.w + vv.w + bb.w, 0.f));
    }
    __syncthreads();    // Bw still holds a2pW1 — reused

    // ---- G4: h1 @ a2pW1 (y1) ; epi: actB += relu -> actB = p0 ----
    zacc(acc);
    wg_ldsm<8, 4, 4>(acc, actA_a, Bw_a, wr, wc, lane);
    __syncthreads();
    cpa_h(Bw, g_Wp2p0, 16, tid);
    epi_add_smem_h(acc, actB, 136, a2p_b1, wm, wn, lane);
    CP_WAIT0;
    __syncthreads();

    // ---- G5: px @ p2pW0 ----
    zacc(acc);
    wg_mma<1>(acc, pxs, 24, Bw, 136, wm, wn, lane);
    __syncthreads();
    cpa_h(Bw, g_Wp2p1, 128, tid);
    epi_smem_h(acc, actA, 136, p2p_b0, wm, wn, lane);
    CP_WAIT0;
    __syncthreads();

    // ---- G6: actA @ p2pW1 ; epi relu -> actA = p1 ----
    zacc(acc);
    wg_ldsm<8, 4, 4>(acc, actA_a, Bw_a, wr, wc, lane);
    __syncthreads();
    cpa_h(Bw, g_Wpl0b, 128, tid);
    epi_smem_h(acc, actA, 136, p2p_b1, wm, wn, lane);
    CP_WAIT0;
    __syncthreads();

    // ---- G7: p1 @ plW0b (no epilogue) ----
    zacc(acc);
    wg_ldsm<8, 4, 4>(acc, actA_a, Bw_a, wr, wc, lane);
    __syncthreads();
    cpa_h(Bw, g_Wpl0a, 128, tid);
    CP_WAIT0;
    __syncthreads();

    // ---- G8: acc += p0 @ plW0a ; epi relu -> actA ----
    wg_ldsm<8, 4, 4>(acc, actB_a, Bw_a, wr, wc, lane);
    __syncthreads();
    cpa_h(Bw, g_Wpl1, 128, tid);
    epi_smem_h(acc, actA, 136, pl_b0, wm, wn, lane);
    CP_WAIT0;
    __syncthreads();

    // ---- G9: actA @ plW1 -> out ----
    zacc(acc);
    wg_ldsm<8, 4, 4>(acc, actA_a, Bw_a, wr, wc, lane);
    epi_gmem_relu(acc, out_pair + tilebase * 128, pl_b1, wm, wn, lane);
}

// ---------------- kernel C: atom finalize ----------------
// grid 64: one batch per CTA (M=64 rows). 8 warps, warp tile 64x16 (MF=4, NF=2).
// smem halves: As 64*136 | Bw0 128*136 | Bw1 128*136
extern "C" __global__ void __launch_bounds__(256, 1)
kC(const float* __restrict__ al_b0, const float* __restrict__ al_b1,
   float* __restrict__ out_atom){
    extern __shared__ __half smh[];
    __half* As  = smh;                    // 64*136
    __half* Bw0 = As + 64 * 136;          // 128*136
    __half* Bw1 = Bw0 + 128 * 136;        // 128*136
    int tid = threadIdx.x, lane = tid & 31, w = tid >> 5;
    int b = blockIdx.x;
    uint32_t As_a = smem_u32(As), B0_a = smem_u32(Bw0), B1_a = smem_u32(Bw1);
    const int wc = w * 16;

    cpa_h(Bw0, g_Wal0a, 128, tid);
    cpa_h(Bw1, g_Wal0b, 128, tid);
    for (int i = tid; i < 64 * 32; i += 256){
        int r = i >> 5, c4 = (i & 31) << 2;
        float4 v = *(const float4*)(g_a0 + b * 8192 + r * 128 + c4);
        *(__half2*)(As + r * 136 + c4)     = __floats2half2_rn(v.x, v.y);
        *(__half2*)(As + r * 136 + c4 + 2) = __floats2half2_rn(v.z, v.w);
    }
    CP_WAIT1;                               // Wal0a resident
    __syncthreads();

    float acc[4][2][4];
#pragma unroll
    for (int m = 0; m < 4; ++m)
#pragma unroll
        for (int n = 0; n < 2; ++n)
#pragma unroll
            for (int q = 0; q < 4; ++q) acc[m][n][q] = 0.f;

    wg_ldsm<8, 4, 2>(acc, As_a, B0_a, 0, wc, lane);
    __syncthreads();
    cpa_h(Bw0, g_Wal1, 128, tid);
    for (int i = tid; i < 64 * 32; i += 256){
        int r = i >> 5, c4 = (i & 31) << 2;
        float4 v = *(const float4*)(g_a1 + b * 8192 + r * 128 + c4);
        *(__half2*)(As + r * 136 + c4)     = __floats2half2_rn(v.x, v.y);
        *(__half2*)(As + r * 136 + c4 + 2) = __floats2half2_rn(v.z, v.w);
    }
    CP_WAIT1;                               // Wal0b resident
    __syncthreads();

    wg_ldsm<8, 4, 2>(acc, As_a, B1_a, 0, wc, lane);
    __syncthreads();
    {   // act = relu(acc + al_b0) -> As (64x136)
        int r0 = lane >> 2;
        int c0 = wc + 2 * (lane & 3);
#pragma unroll
        for (int mf = 0; mf < 4; ++mf)
#pragma unroll
            for (int nf = 0; nf < 2; ++nf){
                int c = c0 + nf * 8;
                float bx = al_b0[c], by = al_b0[c + 1];
                int ra = r0 + mf * 16, rb = ra + 8;
                *(__half2*)(As + ra * 136 + c) =
                    __floats2half2_rn(fmaxf(acc[mf][nf][0] + bx, 0.f), fmaxf(acc[mf][nf][1] + by, 0.f));
                *(__half2*)(As + rb * 136 + c) =
                    __floats2half2_rn(fmaxf(acc[mf][nf][2] + bx, 0.f), fmaxf(acc[mf][nf][3] + by, 0.f));
            }
    }
    CP_WAIT0;                               // Wal1 resident
    __syncthreads();

#pragma unroll
    for (int m = 0; m < 4; ++m)
#pragma unroll
        for (int n = 0; n < 2; ++n)
#pragma unroll
            for (int q = 0; q < 4; ++q) acc[m][n][q] = 0.f;
    wg_ldsm<8, 4, 2>(acc, As_a, B0_a, 0, wc, lane);
    {   // out = relu(acc + al_b1)
        float* dst = out_atom + b * 8192;
        int r0 = lane >> 2;
        int c0 = wc + 2 * (lane & 3);
#pragma unroll
        for (int mf = 0; mf < 4; ++mf)
#pragma unroll
            for (int nf = 0; nf < 2; ++nf){
                int c = c0 + nf * 8;
                float bx = al_b1[c], by = al_b1[c + 1];
                int ra = r0 + mf * 16, rb = ra + 8;
                *(float2*)(dst + ra * 128 + c) = make_float2(fmaxf(acc[mf][nf][0] + bx, 0.f),
                                                             fmaxf(acc[mf][nf][1] + by, 0.f));
                *(float2*)(dst + rb * 128 + c) = make_float2(fmaxf(acc[mf][nf][2] + bx, 0.f),
                                                             fmaxf(acc[mf][nf][3] + by, 0.f));
            }
    }
}

// ---------------------------------------------------------------------------
extern "C" void kernel_launch(void* const* d_in, const int* in_sizes, int n_in,
                              void* d_out, int out_size) {
    const float* atom_x = (const float*)d_in[0];
    const float* pair_x = (const float*)d_in[1];
    const float* a2a_W0 = (const float*)d_in[2];
    const float* a2a_b0 = (const float*)d_in[3];
    const float* a2a_W1 = (const float*)d_in[4];
    const float* a2a_b1 = (const float*)d_in[5];
    const float* p2a_W0 = (const float*)d_in[6];
    const float* p2a_b0 = (const float*)d_in[7];
    const float* p2a_W1 = (const float*)d_in[8];
    const float* p2a_b1 = (const float*)d_in[9];
    const float* al_W0  = (const float*)d_in[10];
    const float* al_b0  = (const float*)d_in[11];
    const float* al_W1  = (const float*)d_in[12];
    const float* al_b1  = (const float*)d_in[13];
    const float* a2p_W0 = (const float*)d_in[14];
    const float* a2p_b0 = (const float*)d_in[15];
    const float* a2p_W1 = (const float*)d_in[16];
    const float* a2p_b1 = (const float*)d_in[17];
    const float* p2p_W0 = (const float*)d_in[18];
    const float* p2p_b0 = (const float*)d_in[19];
    const float* p2p_W1 = (const float*)d_in[20];
    const float* p2p_b1 = (const float*)d_in[21];
    const float* pl_W0  = (const float*)d_in[22];
    const float* pl_b0  = (const float*)d_in[23];
    const float* pl_W1  = (const float*)d_in[24];
    const float* pl_b1  = (const float*)d_in[25];
    float* out = (float*)d_out;

    const int SMEM_A = (3 * 128 * 136) * 2;                              // 104448 B
    const int SMEM_B = (3 * 128 * 136 + 128 * 24) * 2;                   // 110592 B
    const int SMEM_C = (64 * 136 + 2 * 128 * 136) * 2;                   // 87040 B

    cudaFuncSetAttribute(kA, cudaFuncAttributeMaxDynamicSharedMemorySize, SMEM_A);
    cudaFuncSetAttribute(kB, cudaFuncAttributeMaxDynamicSharedMemorySize, SMEM_B);
    cudaFuncSetAttribute(kC, cudaFuncAttributeMaxDynamicSharedMemorySize, SMEM_C);

    kW<<<15, 256>>>(p2a_W0, p2a_W1, p2p_W0, p2p_W1, a2p_W1, pl_W0, pl_W1,
                    al_W0, al_W1, a2a_W0, a2a_W1, a2p_W0);
    kA<<<dim3(32, 3), 256, SMEM_A>>>(atom_x, a2a_b0, a2a_b1);
    kB<<<2048, 256, SMEM_B>>>(pair_x,
                              p2a_b0, p2a_b1, p2p_b0, p2p_b1,
                              a2p_b0, a2p_b1, pl_b0, pl_b1,
                              out + ATOM_OUT);
    kC<<<64, 256, SMEM_C>>>(al_b0, al_b1, out);
}